// round 7
// baseline (speedup 1.0000x reference)
#include <cuda_runtime.h>
#include <cuda_bf16.h>
#include <mma.h>
#include <cstdint>

using namespace nvcuda;

#define NN 50000
#define EE 1000000
#define DD 64
#define TILE 128
#define NT ((EE + TILE - 1) / TILE)   // 7813 (last tile: 64 valid)

// ---------------- scratch (device globals; no allocation allowed) ----------------
__device__ float g_agg[NN * DD];
__device__ float g_trans[NN * 3];
__device__ float g_cnt[NN];
__device__ float g_P[NN * DD];       // h @ We1[0:64] + be1
__device__ float g_Q[NN * DD];       // h @ We1[64:128]

__device__ __forceinline__ void red4(float* p, float a, float b, float c, float d) {
    asm volatile("red.global.add.v4.f32 [%0], {%1, %2, %3, %4};"
                 :: "l"(p), "f"(a), "f"(b), "f"(c), "f"(d) : "memory");
}
__device__ __forceinline__ uint64_t pack2(float x, float y) {
    uint64_t r; asm("mov.b64 %0, {%1, %2};" : "=l"(r) : "f"(x), "f"(y)); return r;
}
__device__ __forceinline__ void unpack2(uint64_t v, float& x, float& y) {
    asm("mov.b64 {%0, %1}, %2;" : "=f"(x), "=f"(y) : "l"(v));
}
__device__ __forceinline__ void fma2(uint64_t& acc, uint64_t a, uint64_t b) {
    asm("fma.rn.f32x2 %0, %1, %2, %0;" : "+l"(acc) : "l"(a), "l"(b));
}
__device__ __forceinline__ uint32_t bf2u(__nv_bfloat162 v) {
    uint32_t u; memcpy(&u, &v, 4); return u;
}

// ---------------- zero scratch ----------------
__global__ void zero_kernel() {
    int i = blockIdx.x * blockDim.x + threadIdx.x;
    int stride = gridDim.x * blockDim.x;
    for (int j = i; j < NN * DD; j += stride) g_agg[j] = 0.f;
    for (int j = i; j < NN * 3;  j += stride) g_trans[j] = 0.f;
    for (int j = i; j < NN;      j += stride) g_cnt[j] = 0.f;
}

// ---------------- pq kernel (unchanged) ----------------
#define PQ_STAGE_BASE 8256
#define PQ_STAGE_STRIDE 2112
#define PQ_SMEM_FLOATS (PQ_STAGE_BASE + 8 * PQ_STAGE_STRIDE)
#define PQ_SMEM_BYTES (PQ_SMEM_FLOATS * 4)

__global__ void __launch_bounds__(256, 1) pq_kernel(
    const float* __restrict__ h,
    const float* __restrict__ We1, const float* __restrict__ be1)
{
    extern __shared__ float s[];
    const int tid = threadIdx.x;
    for (int i = tid; i < 8192; i += 256) s[i] = We1[i];
    for (int i = tid; i < 64;   i += 256) s[8192 + i] = be1[i];
    __syncthreads();

    const int warp = tid >> 5, lane = tid & 31;
    float* stage = s + PQ_STAGE_BASE + warp * PQ_STAGE_STRIDE;
    const int nbase = blockIdx.x * 256 + warp * 32;
    const int n = nbase + lane;

    #pragma unroll 4
    for (int r = 0; r < 32; r++) {
        const int nr = nbase + r;
        if (nr < NN) {
            const float* hp = h + (size_t)nr * 64;
            stage[lane * 33 + r]        = hp[lane];
            stage[(lane + 32) * 33 + r] = hp[lane + 32];
        } else {
            stage[lane * 33 + r]        = 0.f;
            stage[(lane + 32) * 33 + r] = 0.f;
        }
    }
    __syncwarp();

    uint64_t acc2[32];
    {
        const uint64_t* b2 = (const uint64_t*)(s + 8192);
        #pragma unroll
        for (int t = 0; t < 32; t++) acc2[t] = b2[t];
    }
    for (int k = 0; k < 64; k++) {
        const float x = stage[k * 33 + lane];
        const uint64_t xx = pack2(x, x);
        const ulonglong2* w = (const ulonglong2*)(s + k * 64);
        #pragma unroll
        for (int t = 0; t < 16; t++) {
            ulonglong2 wv = w[t];
            fma2(acc2[2 * t + 0], xx, wv.x);
            fma2(acc2[2 * t + 1], xx, wv.y);
        }
    }
    if (n < NN) {
        float* op = g_P + (size_t)n * 64;
        #pragma unroll
        for (int t = 0; t < 16; t++) {
            float a, b, c, d;
            unpack2(acc2[2 * t + 0], a, b);
            unpack2(acc2[2 * t + 1], c, d);
            float4 v; v.x = a; v.y = b; v.z = c; v.w = d;
            *(float4*)(op + 4 * t) = v;
        }
    }

    #pragma unroll
    for (int t = 0; t < 32; t++) acc2[t] = 0ull;
    for (int k = 0; k < 64; k++) {
        const float x = stage[k * 33 + lane];
        const uint64_t xx = pack2(x, x);
        const ulonglong2* w = (const ulonglong2*)(s + (64 + k) * 64);
        #pragma unroll
        for (int t = 0; t < 16; t++) {
            ulonglong2 wv = w[t];
            fma2(acc2[2 * t + 0], xx, wv.x);
            fma2(acc2[2 * t + 1], xx, wv.y);
        }
    }
    if (n < NN) {
        float* op = g_Q + (size_t)n * 64;
        #pragma unroll
        for (int t = 0; t < 16; t++) {
            float a, b, c, d;
            unpack2(acc2[2 * t + 0], a, b);
            unpack2(acc2[2 * t + 1], c, d);
            float4 v; v.x = a; v.y = b; v.z = c; v.w = d;
            *(float4*)(op + 4 * t) = v;
        }
    }
}

// ---------------- edge kernel: wmma bf16 hi/lo, 128-edge tiles, 256 threads ----------------
// SMEM byte map:
//   floats s[0..255]: w128 @0, be2 @64, bc1 @128, wc2 @192
//   bf16 W tiles (stride 72): WE2H @4096, WE2L @13312, WC1H @22528, WC1L @31744
//   bf16 A tiles (stride 72): AH @40960 (18432 B), AL @59392 (18432 B)
//   f32 D (stride 68): @77824 (34816 B)  -> total 112640
#define EB_WE2H 4096
#define EB_WE2L 13312
#define EB_WC1H 22528
#define EB_WC1L 31744
#define EB_AH   40960
#define EB_AL   59392
#define EB_D    77824
#define EDGE_SMEM_BYTES 112640

__device__ __forceinline__ void gemm_hilo(char* sc, int whOff, int wlOff, int wid) {
    wmma::fragment<wmma::accumulator, 16, 16, 16, float> acc[4];
    #pragma unroll
    for (int ct = 0; ct < 4; ct++) wmma::fill_fragment(acc[ct], 0.f);

    const __nv_bfloat16* Ah = (const __nv_bfloat16*)(sc + EB_AH) + wid * 16 * 72;
    const __nv_bfloat16* Al = (const __nv_bfloat16*)(sc + EB_AL) + wid * 16 * 72;
    const __nv_bfloat16* Wh = (const __nv_bfloat16*)(sc + whOff);
    const __nv_bfloat16* Wl = (const __nv_bfloat16*)(sc + wlOff);

    #pragma unroll
    for (int k0 = 0; k0 < 4; k0++) {
        wmma::fragment<wmma::matrix_a, 16, 16, 16, __nv_bfloat16, wmma::row_major> a_h, a_l;
        wmma::load_matrix_sync(a_h, Ah + k0 * 16, 72);
        wmma::load_matrix_sync(a_l, Al + k0 * 16, 72);
        #pragma unroll
        for (int ct = 0; ct < 4; ct++) {
            wmma::fragment<wmma::matrix_b, 16, 16, 16, __nv_bfloat16, wmma::row_major> b_h, b_l;
            wmma::load_matrix_sync(b_h, Wh + k0 * 16 * 72 + ct * 16, 72);
            wmma::load_matrix_sync(b_l, Wl + k0 * 16 * 72 + ct * 16, 72);
            wmma::mma_sync(acc[ct], a_h, b_h, acc[ct]);
            wmma::mma_sync(acc[ct], a_l, b_h, acc[ct]);
            wmma::mma_sync(acc[ct], a_h, b_l, acc[ct]);
        }
    }
    float* Dp = (float*)(sc + EB_D) + wid * 16 * 68;
    #pragma unroll
    for (int ct = 0; ct < 4; ct++)
        wmma::store_matrix_sync(Dp + ct * 16, acc[ct], 68, wmma::mem_row_major);
}

__global__ void __launch_bounds__(256, 2) edge_kernel(
    const float* __restrict__ coord,
    const int* __restrict__ ei,
    const float* __restrict__ We1,   // row 128 only
    const float* __restrict__ We2,
    const float* __restrict__ Wc1, const float* __restrict__ be2,
    const float* __restrict__ bc1, const float* __restrict__ Wc2)
{
    extern __shared__ __align__(16) char sc[];
    float* s = (float*)sc;

    const int tid = threadIdx.x;
    const int wid = tid >> 5;

    // scalars
    for (int i = tid; i < 64; i += 256) {
        s[i]        = We1[128 * 64 + i];
        s[64 + i]   = be2[i];
        s[128 + i]  = bc1[i];
        s[192 + i]  = Wc2[i];
    }
    // weight tiles: [k][n] row-major, stride 72, hi/lo bf16
    for (int i = tid; i < 4096; i += 256) {
        const int k = i >> 6, n = i & 63;
        {
            float v = We2[i];
            __nv_bfloat16 hb = __float2bfloat16(v);
            __nv_bfloat16 lb = __float2bfloat16(v - __bfloat162float(hb));
            ((__nv_bfloat16*)(sc + EB_WE2H))[k * 72 + n] = hb;
            ((__nv_bfloat16*)(sc + EB_WE2L))[k * 72 + n] = lb;
        }
        {
            float v = Wc1[i];
            __nv_bfloat16 hb = __float2bfloat16(v);
            __nv_bfloat16 lb = __float2bfloat16(v - __bfloat162float(hb));
            ((__nv_bfloat16*)(sc + EB_WC1H))[k * 72 + n] = hb;
            ((__nv_bfloat16*)(sc + EB_WC1L))[k * 72 + n] = lb;
        }
    }

    const int r = tid >> 1;          // edge row within tile (0..127)
    const int hh = tid & 1;          // column half (0/1)
    const int c0 = hh * 32;

    for (int t = blockIdx.x; t < NT; t += gridDim.x) {
        __syncthreads();   // A/D tiles free from previous iteration

        // per-thread edge data (pair threads load the same addresses -> broadcast)
        const int e = t * TILE + r;
        const bool valid = e < EE;
        const int erow = valid ? ei[e] : 0;
        const int ecol = valid ? ei[EE + e] : 0;
        const float dx = coord[erow * 3 + 0] - coord[ecol * 3 + 0];
        const float dy = coord[erow * 3 + 1] - coord[ecol * 3 + 1];
        const float dz = coord[erow * 3 + 2] - coord[ecol * 3 + 2];
        const float rad = dx * dx + dy * dy + dz * dz;

        // ---- build A1 = relu(P[row]+Q[col]+rad*w128) hi/lo; thread = (row, half)
        {
            const float4* Pp = (const float4*)(g_P + (size_t)erow * 64 + c0);
            const float4* Qp = (const float4*)(g_Q + (size_t)ecol * 64 + c0);
            const float4* wp = (const float4*)(s + c0);
            uint2* ah = (uint2*)(sc + EB_AH + r * 144 + hh * 64);
            uint2* al = (uint2*)(sc + EB_AL + r * 144 + hh * 64);
            #pragma unroll
            for (int j = 0; j < 8; j++) {
                float4 p = Pp[j], q = Qp[j], w = wp[j];
                const float v0 = fmaxf(fmaf(rad, w.x, p.x + q.x), 0.f);
                const float v1 = fmaxf(fmaf(rad, w.y, p.y + q.y), 0.f);
                const float v2 = fmaxf(fmaf(rad, w.z, p.z + q.z), 0.f);
                const float v3 = fmaxf(fmaf(rad, w.w, p.w + q.w), 0.f);
                __nv_bfloat162 h01 = __floats2bfloat162_rn(v0, v1);
                __nv_bfloat162 h23 = __floats2bfloat162_rn(v2, v3);
                __nv_bfloat162 l01 = __floats2bfloat162_rn(v0 - __bfloat162float(h01.x),
                                                           v1 - __bfloat162float(h01.y));
                __nv_bfloat162 l23 = __floats2bfloat162_rn(v2 - __bfloat162float(h23.x),
                                                           v3 - __bfloat162float(h23.y));
                ah[j] = make_uint2(bf2u(h01), bf2u(h23));
                al[j] = make_uint2(bf2u(l01), bf2u(l23));
            }
        }
        __syncthreads();

        // ---- GEMM1: D = A1 @ We2 ----
        gemm_hilo(sc, EB_WE2H, EB_WE2L, wid);
        __syncthreads();

        // ---- epilogue 1: ef = relu(D + be2); scatter; build A2 hi/lo ----
        {
            const float4* Dr = (const float4*)((float*)(sc + EB_D) + r * 68 + c0);
            const float4* bb = (const float4*)(s + 64 + c0);
            float ef[32];
            #pragma unroll
            for (int j = 0; j < 8; j++) {
                float4 d = Dr[j], b = bb[j];
                ef[4 * j + 0] = fmaxf(d.x + b.x, 0.f);
                ef[4 * j + 1] = fmaxf(d.y + b.y, 0.f);
                ef[4 * j + 2] = fmaxf(d.z + b.z, 0.f);
                ef[4 * j + 3] = fmaxf(d.w + b.w, 0.f);
            }
            if (valid) {
                float* dst = g_agg + (size_t)erow * 64 + c0;
                #pragma unroll
                for (int j = 0; j < 8; j++)
                    red4(dst + 4 * j, ef[4 * j], ef[4 * j + 1], ef[4 * j + 2], ef[4 * j + 3]);
            }

            uint2* ah = (uint2*)(sc + EB_AH + r * 144 + hh * 64);
            uint2* al = (uint2*)(sc + EB_AL + r * 144 + hh * 64);
            #pragma unroll
            for (int j = 0; j < 8; j++) {
                const float v0 = ef[4 * j + 0], v1 = ef[4 * j + 1];
                const float v2 = ef[4 * j + 2], v3 = ef[4 * j + 3];
                __nv_bfloat162 h01 = __floats2bfloat162_rn(v0, v1);
                __nv_bfloat162 h23 = __floats2bfloat162_rn(v2, v3);
                __nv_bfloat162 l01 = __floats2bfloat162_rn(v0 - __bfloat162float(h01.x),
                                                           v1 - __bfloat162float(h01.y));
                __nv_bfloat162 l23 = __floats2bfloat162_rn(v2 - __bfloat162float(h23.x),
                                                           v3 - __bfloat162float(h23.y));
                ah[j] = make_uint2(bf2u(h01), bf2u(h23));
                al[j] = make_uint2(bf2u(l01), bf2u(l23));
            }
        }
        __syncthreads();

        // ---- GEMM2: D = EF @ Wc1 ----
        gemm_hilo(sc, EB_WC1H, EB_WC1L, wid);
        __syncthreads();

        // ---- epilogue 2: gate = relu(D + bc1) . wc2; clamp; coord atomics ----
        {
            const float4* Dr = (const float4*)((float*)(sc + EB_D) + r * 68 + c0);
            const float4* bb = (const float4*)(s + 128 + c0);
            const float4* wc = (const float4*)(s + 192 + c0);
            float g = 0.f;
            #pragma unroll
            for (int j = 0; j < 8; j++) {
                float4 d = Dr[j], b = bb[j], w = wc[j];
                g += fmaxf(d.x + b.x, 0.f) * w.x;
                g += fmaxf(d.y + b.y, 0.f) * w.y;
                g += fmaxf(d.z + b.z, 0.f) * w.z;
                g += fmaxf(d.w + b.w, 0.f) * w.w;
            }
            g += __shfl_xor_sync(0xFFFFFFFFu, g, 1);
            if (hh == 0 && valid) {
                const float tx = fminf(fmaxf(dx * g, -100.f), 100.f);
                const float ty = fminf(fmaxf(dy * g, -100.f), 100.f);
                const float tz = fminf(fmaxf(dz * g, -100.f), 100.f);
                atomicAdd(&g_trans[erow * 3 + 0], tx);
                atomicAdd(&g_trans[erow * 3 + 1], ty);
                atomicAdd(&g_trans[erow * 3 + 2], tz);
                atomicAdd(&g_cnt[erow], 1.f);
            }
        }
    }
}

// ---------------- node kernel (unchanged) ----------------
#define NODE_STAGE_BASE 12416
#define NODE_STAGE_STRIDE 4224
#define NODE_SMEM_FLOATS (NODE_STAGE_BASE + 8 * NODE_STAGE_STRIDE)
#define NODE_SMEM_BYTES (NODE_SMEM_FLOATS * 4)

__global__ void __launch_bounds__(256, 1) node_kernel(
    const float* __restrict__ h,
    const float* __restrict__ Wn1, const float* __restrict__ bn1,
    const float* __restrict__ Wn2, const float* __restrict__ bn2,
    float* __restrict__ out_h, float* __restrict__ out_c)
{
    extern __shared__ float s[];
    const int tid = threadIdx.x;
    for (int i = tid; i < 8192; i += 256) s[i]         = Wn1[i];
    for (int i = tid; i < 64;   i += 256) s[8192 + i]  = bn1[i];
    for (int i = tid; i < 4096; i += 256) s[8256 + i]  = Wn2[i];
    for (int i = tid; i < 64;   i += 256) s[12352 + i] = bn2[i];
    __syncthreads();

    const int warp = tid >> 5, lane = tid & 31;
    float* stage = s + NODE_STAGE_BASE + warp * NODE_STAGE_STRIDE;

    const int nbase = blockIdx.x * 256 + warp * 32;
    const int n = nbase + lane;

    #pragma unroll 4
    for (int r = 0; r < 32; r++) {
        const int nr = nbase + r;
        if (nr < NN) {
            const float* hp = h + (size_t)nr * 64;
            const float* ap = g_agg + (size_t)nr * 64;
            stage[(lane)      * 33 + r] = hp[lane];
            stage[(lane + 32) * 33 + r] = hp[lane + 32];
            stage[(lane + 64) * 33 + r] = ap[lane];
            stage[(lane + 96) * 33 + r] = ap[lane + 32];
        } else {
            stage[(lane)      * 33 + r] = 0.f;
            stage[(lane + 32) * 33 + r] = 0.f;
            stage[(lane + 64) * 33 + r] = 0.f;
            stage[(lane + 96) * 33 + r] = 0.f;
        }
    }
    __syncwarp();

    uint64_t acc2[32];
    float m[64];

    {
        const uint64_t* b2 = (const uint64_t*)(s + 8192);
        #pragma unroll
        for (int t = 0; t < 32; t++) acc2[t] = b2[t];
    }
    for (int k = 0; k < 128; k++) {
        const float x = stage[k * 33 + lane];
        const uint64_t xx = pack2(x, x);
        const ulonglong2* w = (const ulonglong2*)(s + k * 64);
        #pragma unroll
        for (int t = 0; t < 16; t++) {
            ulonglong2 wv = w[t];
            fma2(acc2[2 * t + 0], xx, wv.x);
            fma2(acc2[2 * t + 1], xx, wv.y);
        }
    }
    #pragma unroll
    for (int t = 0; t < 32; t++) {
        float a, b; unpack2(acc2[t], a, b);
        m[2 * t + 0] = fmaxf(a, 0.f);
        m[2 * t + 1] = fmaxf(b, 0.f);
    }

    {
        const uint64_t* b2 = (const uint64_t*)(s + 12352);
        #pragma unroll
        for (int t = 0; t < 32; t++) acc2[t] = b2[t];
    }
    #pragma unroll
    for (int k = 0; k < 64; k++) {
        const uint64_t xx = pack2(m[k], m[k]);
        const ulonglong2* w = (const ulonglong2*)(s + 8256 + k * 64);
        #pragma unroll
        for (int t = 0; t < 16; t++) {
            ulonglong2 wv = w[t];
            fma2(acc2[2 * t + 0], xx, wv.x);
            fma2(acc2[2 * t + 1], xx, wv.y);
        }
    }

    if (n < NN) {
        float* op = out_h + (size_t)n * 64;
        #pragma unroll
        for (int t = 0; t < 16; t++) {
            float a, b, c, d;
            unpack2(acc2[2 * t + 0], a, b);
            unpack2(acc2[2 * t + 1], c, d);
            float4 v;
            v.x = stage[(4 * t + 0) * 33 + lane] + a;
            v.y = stage[(4 * t + 1) * 33 + lane] + b;
            v.z = stage[(4 * t + 2) * 33 + lane] + c;
            v.w = stage[(4 * t + 3) * 33 + lane] + d;
            *(float4*)(op + 4 * t) = v;
        }
        const float inv = 1.f / fmaxf(g_cnt[n], 1.f);
        out_c[n * 3 + 0] = g_trans[n * 3 + 0] * inv;
        out_c[n * 3 + 1] = g_trans[n * 3 + 1] * inv;
        out_c[n * 3 + 2] = g_trans[n * 3 + 2] * inv;
    }
}

// ---------------- launch ----------------
extern "C" void kernel_launch(void* const* d_in, const int* in_sizes, int n_in,
                              void* d_out, int out_size)
{
    const float* h     = (const float*)d_in[0];
    const float* coord = (const float*)d_in[1];
    const int*   ei    = (const int*)  d_in[2];
    const float* We1 = (const float*)d_in[3];
    const float* be1 = (const float*)d_in[4];
    const float* We2 = (const float*)d_in[5];
    const float* be2 = (const float*)d_in[6];
    const float* Wn1 = (const float*)d_in[7];
    const float* bn1 = (const float*)d_in[8];
    const float* Wn2 = (const float*)d_in[9];
    const float* bn2 = (const float*)d_in[10];
    const float* Wc1 = (const float*)d_in[11];
    const float* bc1 = (const float*)d_in[12];
    const float* Wc2 = (const float*)d_in[13];

    float* out_h = (float*)d_out;                   // [N, 64]
    float* out_c = (float*)d_out + (size_t)NN * DD; // [N, 3]

    cudaFuncSetAttribute(pq_kernel,   cudaFuncAttributeMaxDynamicSharedMemorySize, PQ_SMEM_BYTES);
    cudaFuncSetAttribute(edge_kernel, cudaFuncAttributeMaxDynamicSharedMemorySize, EDGE_SMEM_BYTES);
    cudaFuncSetAttribute(node_kernel, cudaFuncAttributeMaxDynamicSharedMemorySize, NODE_SMEM_BYTES);

    zero_kernel<<<1024, 256>>>();
    pq_kernel<<<(NN + 255) / 256, 256, PQ_SMEM_BYTES>>>(h, We1, be1);
    edge_kernel<<<296, 256, EDGE_SMEM_BYTES>>>(coord, ei, We1, We2, Wc1, be2, bc1, Wc2);
    node_kernel<<<(NN + 255) / 256, 256, NODE_SMEM_BYTES>>>(h, Wn1, bn1, Wn2, bn2,
                                                            out_h, out_c);
}

// round 8
// speedup vs baseline: 1.1373x; 1.1373x over previous
#include <cuda_runtime.h>
#include <cuda_bf16.h>
#include <mma.h>
#include <cstdint>

using namespace nvcuda;

#define NN 50000
#define EE 1000000
#define DD 64
#define TILE 64
#define NT (EE / TILE)   // 15625 exactly

// ---------------- scratch (device globals; no allocation allowed) ----------------
__device__ float g_agg[NN * DD];
__device__ float g_trans[NN * 3];
__device__ float g_cnt[NN];
__device__ float g_P[NN * DD];       // h @ We1[0:64] + be1
__device__ float g_Q[NN * DD];       // h @ We1[64:128]

__device__ __forceinline__ void red4(float* p, float a, float b, float c, float d) {
    asm volatile("red.global.add.v4.f32 [%0], {%1, %2, %3, %4};"
                 :: "l"(p), "f"(a), "f"(b), "f"(c), "f"(d) : "memory");
}
__device__ __forceinline__ uint64_t pack2(float x, float y) {
    uint64_t r; asm("mov.b64 %0, {%1, %2};" : "=l"(r) : "f"(x), "f"(y)); return r;
}
__device__ __forceinline__ void unpack2(uint64_t v, float& x, float& y) {
    asm("mov.b64 {%0, %1}, %2;" : "=f"(x), "=f"(y) : "l"(v));
}
__device__ __forceinline__ void fma2(uint64_t& acc, uint64_t a, uint64_t b) {
    asm("fma.rn.f32x2 %0, %1, %2, %0;" : "+l"(acc) : "l"(a), "l"(b));
}
__device__ __forceinline__ uint32_t bf2u(__nv_bfloat162 v) {
    uint32_t u; memcpy(&u, &v, 4); return u;
}

// ---------------- zero scratch ----------------
__global__ void zero_kernel() {
    int i = blockIdx.x * blockDim.x + threadIdx.x;
    int stride = gridDim.x * blockDim.x;
    for (int j = i; j < NN * DD; j += stride) g_agg[j] = 0.f;
    for (int j = i; j < NN * 3;  j += stride) g_trans[j] = 0.f;
    for (int j = i; j < NN;      j += stride) g_cnt[j] = 0.f;
}

// ---------------- pq kernel (unchanged) ----------------
#define PQ_STAGE_BASE 8256
#define PQ_STAGE_STRIDE 2112
#define PQ_SMEM_FLOATS (PQ_STAGE_BASE + 8 * PQ_STAGE_STRIDE)
#define PQ_SMEM_BYTES (PQ_SMEM_FLOATS * 4)

__global__ void __launch_bounds__(256, 1) pq_kernel(
    const float* __restrict__ h,
    const float* __restrict__ We1, const float* __restrict__ be1)
{
    extern __shared__ float s[];
    const int tid = threadIdx.x;
    for (int i = tid; i < 8192; i += 256) s[i] = We1[i];
    for (int i = tid; i < 64;   i += 256) s[8192 + i] = be1[i];
    __syncthreads();

    const int warp = tid >> 5, lane = tid & 31;
    float* stage = s + PQ_STAGE_BASE + warp * PQ_STAGE_STRIDE;
    const int nbase = blockIdx.x * 256 + warp * 32;
    const int n = nbase + lane;

    #pragma unroll 4
    for (int r = 0; r < 32; r++) {
        const int nr = nbase + r;
        if (nr < NN) {
            const float* hp = h + (size_t)nr * 64;
            stage[lane * 33 + r]        = hp[lane];
            stage[(lane + 32) * 33 + r] = hp[lane + 32];
        } else {
            stage[lane * 33 + r]        = 0.f;
            stage[(lane + 32) * 33 + r] = 0.f;
        }
    }
    __syncwarp();

    uint64_t acc2[32];
    {
        const uint64_t* b2 = (const uint64_t*)(s + 8192);
        #pragma unroll
        for (int t = 0; t < 32; t++) acc2[t] = b2[t];
    }
    for (int k = 0; k < 64; k++) {
        const float x = stage[k * 33 + lane];
        const uint64_t xx = pack2(x, x);
        const ulonglong2* w = (const ulonglong2*)(s + k * 64);
        #pragma unroll
        for (int t = 0; t < 16; t++) {
            ulonglong2 wv = w[t];
            fma2(acc2[2 * t + 0], xx, wv.x);
            fma2(acc2[2 * t + 1], xx, wv.y);
        }
    }
    if (n < NN) {
        float* op = g_P + (size_t)n * 64;
        #pragma unroll
        for (int t = 0; t < 16; t++) {
            float a, b, c, d;
            unpack2(acc2[2 * t + 0], a, b);
            unpack2(acc2[2 * t + 1], c, d);
            float4 v; v.x = a; v.y = b; v.z = c; v.w = d;
            *(float4*)(op + 4 * t) = v;
        }
    }

    #pragma unroll
    for (int t = 0; t < 32; t++) acc2[t] = 0ull;
    for (int k = 0; k < 64; k++) {
        const float x = stage[k * 33 + lane];
        const uint64_t xx = pack2(x, x);
        const ulonglong2* w = (const ulonglong2*)(s + (64 + k) * 64);
        #pragma unroll
        for (int t = 0; t < 16; t++) {
            ulonglong2 wv = w[t];
            fma2(acc2[2 * t + 0], xx, wv.x);
            fma2(acc2[2 * t + 1], xx, wv.y);
        }
    }
    if (n < NN) {
        float* op = g_Q + (size_t)n * 64;
        #pragma unroll
        for (int t = 0; t < 16; t++) {
            float a, b, c, d;
            unpack2(acc2[2 * t + 0], a, b);
            unpack2(acc2[2 * t + 1], c, d);
            float4 v; v.x = a; v.y = b; v.z = c; v.w = d;
            *(float4*)(op + 4 * t) = v;
        }
    }
}

// ---------------- edge kernel: wmma bf16 hi/lo, 64-edge tiles, D overlays A ----------------
// 128 threads/CTA, 3 CTAs/SM.
// SMEM byte map:
//   floats s[]: w128 @0, be2 @64, bc1 @128, wc2 @192,
//               irow @256(int), icol @320, frad @384, fdx @448, fdy @512, fdz @576
//   bf16 W tiles (stride 72): WE2H @4096, WE2L @13312, WC1H @22528, WC1L @31744
//   A/D per-warp blocks @40960, 4 blocks x 4736 B:
//     [hi 16x72 bf16 = 2304 | lo 16x72 bf16 = 2304 | pad 128]
//     D (f32, 16x68 = 4352 B) OVERLAYS block start after each GEMM
//   total = 40960 + 4*4736 = 59904
#define EB_WE2H 4096
#define EB_WE2L 13312
#define EB_WC1H 22528
#define EB_WC1L 31744
#define EB_A    40960
#define AB_STRIDE 4736
#define AB_LO   2304
#define EDGE_SMEM_BYTES 59904

__device__ __forceinline__ void gemm_hilo(char* sc, int whOff, int wlOff, int wid) {
    wmma::fragment<wmma::accumulator, 16, 16, 16, float> acc[4];
    #pragma unroll
    for (int ct = 0; ct < 4; ct++) wmma::fill_fragment(acc[ct], 0.f);

    char* ab = sc + EB_A + wid * AB_STRIDE;
    const __nv_bfloat16* Ah = (const __nv_bfloat16*)(ab);
    const __nv_bfloat16* Al = (const __nv_bfloat16*)(ab + AB_LO);
    const __nv_bfloat16* Wh = (const __nv_bfloat16*)(sc + whOff);
    const __nv_bfloat16* Wl = (const __nv_bfloat16*)(sc + wlOff);

    #pragma unroll
    for (int k0 = 0; k0 < 4; k0++) {
        wmma::fragment<wmma::matrix_a, 16, 16, 16, __nv_bfloat16, wmma::row_major> a_h, a_l;
        wmma::load_matrix_sync(a_h, Ah + k0 * 16, 72);
        wmma::load_matrix_sync(a_l, Al + k0 * 16, 72);
        #pragma unroll
        for (int ct = 0; ct < 4; ct++) {
            wmma::fragment<wmma::matrix_b, 16, 16, 16, __nv_bfloat16, wmma::row_major> b_h, b_l;
            wmma::load_matrix_sync(b_h, Wh + k0 * 16 * 72 + ct * 16, 72);
            wmma::load_matrix_sync(b_l, Wl + k0 * 16 * 72 + ct * 16, 72);
            wmma::mma_sync(acc[ct], a_h, b_h, acc[ct]);
            wmma::mma_sync(acc[ct], a_l, b_h, acc[ct]);
            wmma::mma_sync(acc[ct], a_h, b_l, acc[ct]);
        }
    }
    // D overlays this warp's own A block (A fragments already consumed)
    float* Dp = (float*)ab;
    #pragma unroll
    for (int ct = 0; ct < 4; ct++)
        wmma::store_matrix_sync(Dp + ct * 16, acc[ct], 68, wmma::mem_row_major);
}

__global__ void __launch_bounds__(128, 3) edge_kernel(
    const float* __restrict__ coord,
    const int* __restrict__ ei,
    const float* __restrict__ We1,   // row 128 only
    const float* __restrict__ We2,
    const float* __restrict__ Wc1, const float* __restrict__ be2,
    const float* __restrict__ bc1, const float* __restrict__ Wc2)
{
    extern __shared__ __align__(16) char sc[];
    float* s = (float*)sc;

    const int tid = threadIdx.x;
    const int wid = tid >> 5;

    // scalars
    for (int i = tid; i < 64; i += 128) {
        s[i]        = We1[128 * 64 + i];
        s[64 + i]   = be2[i];
        s[128 + i]  = bc1[i];
        s[192 + i]  = Wc2[i];
    }
    // weight tiles: [k][n] row-major, stride 72, hi/lo bf16
    for (int i = tid; i < 4096; i += 128) {
        const int k = i >> 6, n = i & 63;
        {
            float v = We2[i];
            __nv_bfloat16 hb = __float2bfloat16(v);
            __nv_bfloat16 lb = __float2bfloat16(v - __bfloat162float(hb));
            ((__nv_bfloat16*)(sc + EB_WE2H))[k * 72 + n] = hb;
            ((__nv_bfloat16*)(sc + EB_WE2L))[k * 72 + n] = lb;
        }
        {
            float v = Wc1[i];
            __nv_bfloat16 hb = __float2bfloat16(v);
            __nv_bfloat16 lb = __float2bfloat16(v - __bfloat162float(hb));
            ((__nv_bfloat16*)(sc + EB_WC1H))[k * 72 + n] = hb;
            ((__nv_bfloat16*)(sc + EB_WC1L))[k * 72 + n] = lb;
        }
    }

    int*   irow = (int*)(s + 256);
    int*   icol = (int*)(s + 320);
    float* frad = s + 384;
    float* fdx  = s + 448;
    float* fdy  = s + 512;
    float* fdz  = s + 576;

    const int r = tid >> 1;          // edge row within tile (0..63)
    const int hh = tid & 1;          // column half (0/1)
    const int c0 = hh * 32;
    char* abR = sc + EB_A + (r >> 4) * AB_STRIDE;   // block of the warp owning row r
    const int rr16 = r & 15;

    for (int t = blockIdx.x; t < NT; t += gridDim.x) {
        __syncthreads();   // protect smem from previous iteration
        if (tid < TILE) {
            const int e = t * TILE + tid;
            const int row = ei[e];
            const int col = ei[EE + e];
            irow[tid] = row;
            icol[tid] = col;
            const float dx = coord[row * 3 + 0] - coord[col * 3 + 0];
            const float dy = coord[row * 3 + 1] - coord[col * 3 + 1];
            const float dz = coord[row * 3 + 2] - coord[col * 3 + 2];
            fdx[tid] = dx; fdy[tid] = dy; fdz[tid] = dz;
            frad[tid] = dx * dx + dy * dy + dz * dz;
        }
        __syncthreads();

        // ---- build A1 = relu(P[row]+Q[col]+rad*w128) hi/lo; thread = (row, half)
        {
            const int rrw = irow[r], cc = icol[r];
            const float rad = frad[r];
            const float4* Pp = (const float4*)(g_P + (size_t)rrw * 64 + c0);
            const float4* Qp = (const float4*)(g_Q + (size_t)cc * 64 + c0);
            const float4* wp = (const float4*)(s + c0);
            uint2* ah = (uint2*)(abR + rr16 * 144 + hh * 64);
            uint2* al = (uint2*)(abR + AB_LO + rr16 * 144 + hh * 64);
            #pragma unroll
            for (int j = 0; j < 8; j++) {
                float4 p = Pp[j], q = Qp[j], w = wp[j];
                const float v0 = fmaxf(fmaf(rad, w.x, p.x + q.x), 0.f);
                const float v1 = fmaxf(fmaf(rad, w.y, p.y + q.y), 0.f);
                const float v2 = fmaxf(fmaf(rad, w.z, p.z + q.z), 0.f);
                const float v3 = fmaxf(fmaf(rad, w.w, p.w + q.w), 0.f);
                __nv_bfloat162 h01 = __floats2bfloat162_rn(v0, v1);
                __nv_bfloat162 h23 = __floats2bfloat162_rn(v2, v3);
                __nv_bfloat162 l01 = __floats2bfloat162_rn(v0 - __bfloat162float(h01.x),
                                                           v1 - __bfloat162float(h01.y));
                __nv_bfloat162 l23 = __floats2bfloat162_rn(v2 - __bfloat162float(h23.x),
                                                           v3 - __bfloat162float(h23.y));
                ah[j] = make_uint2(bf2u(h01), bf2u(h23));
                al[j] = make_uint2(bf2u(l01), bf2u(l23));
            }
        }
        __syncthreads();

        // ---- GEMM1: D = A1 @ We2 (D overlays A1) ----
        gemm_hilo(sc, EB_WE2H, EB_WE2L, wid);
        __syncthreads();

        // ---- epilogue 1a: read D into regs ----
        float ef[32];
        {
            const float4* Dr = (const float4*)((float*)abR + rr16 * 68 + c0);
            const float4* bb = (const float4*)(s + 64 + c0);
            #pragma unroll
            for (int j = 0; j < 8; j++) {
                float4 d = Dr[j], b = bb[j];
                ef[4 * j + 0] = fmaxf(d.x + b.x, 0.f);
                ef[4 * j + 1] = fmaxf(d.y + b.y, 0.f);
                ef[4 * j + 2] = fmaxf(d.z + b.z, 0.f);
                ef[4 * j + 3] = fmaxf(d.w + b.w, 0.f);
            }
        }
        __syncthreads();   // all D reads done before A2 writes overwrite the blocks

        // ---- epilogue 1b: scatter + build A2 hi/lo ----
        {
            float* dst = g_agg + (size_t)irow[r] * 64 + c0;
            #pragma unroll
            for (int j = 0; j < 8; j++)
                red4(dst + 4 * j, ef[4 * j], ef[4 * j + 1], ef[4 * j + 2], ef[4 * j + 3]);

            uint2* ah = (uint2*)(abR + rr16 * 144 + hh * 64);
            uint2* al = (uint2*)(abR + AB_LO + rr16 * 144 + hh * 64);
            #pragma unroll
            for (int j = 0; j < 8; j++) {
                const float v0 = ef[4 * j + 0], v1 = ef[4 * j + 1];
                const float v2 = ef[4 * j + 2], v3 = ef[4 * j + 3];
                __nv_bfloat162 h01 = __floats2bfloat162_rn(v0, v1);
                __nv_bfloat162 h23 = __floats2bfloat162_rn(v2, v3);
                __nv_bfloat162 l01 = __floats2bfloat162_rn(v0 - __bfloat162float(h01.x),
                                                           v1 - __bfloat162float(h01.y));
                __nv_bfloat162 l23 = __floats2bfloat162_rn(v2 - __bfloat162float(h23.x),
                                                           v3 - __bfloat162float(h23.y));
                ah[j] = make_uint2(bf2u(h01), bf2u(h23));
                al[j] = make_uint2(bf2u(l01), bf2u(l23));
            }
        }
        __syncthreads();

        // ---- GEMM2: D = EF @ Wc1 (D overlays A2) ----
        gemm_hilo(sc, EB_WC1H, EB_WC1L, wid);
        __syncthreads();

        // ---- epilogue 2: gate = relu(D + bc1) . wc2; clamp; coord atomics ----
        {
            const float4* Dr = (const float4*)((float*)abR + rr16 * 68 + c0);
            const float4* bb = (const float4*)(s + 128 + c0);
            const float4* wc = (const float4*)(s + 192 + c0);
            float g = 0.f;
            #pragma unroll
            for (int j = 0; j < 8; j++) {
                float4 d = Dr[j], b = bb[j], w = wc[j];
                g += fmaxf(d.x + b.x, 0.f) * w.x;
                g += fmaxf(d.y + b.y, 0.f) * w.y;
                g += fmaxf(d.z + b.z, 0.f) * w.z;
                g += fmaxf(d.w + b.w, 0.f) * w.w;
            }
            g += __shfl_xor_sync(0xFFFFFFFFu, g, 1);
            if (hh == 0) {
                const int row = irow[r];
                const float tx = fminf(fmaxf(fdx[r] * g, -100.f), 100.f);
                const float ty = fminf(fmaxf(fdy[r] * g, -100.f), 100.f);
                const float tz = fminf(fmaxf(fdz[r] * g, -100.f), 100.f);
                atomicAdd(&g_trans[row * 3 + 0], tx);
                atomicAdd(&g_trans[row * 3 + 1], ty);
                atomicAdd(&g_trans[row * 3 + 2], tz);
                atomicAdd(&g_cnt[row], 1.f);
            }
        }
    }
}

// ---------------- node kernel (unchanged) ----------------
#define NODE_STAGE_BASE 12416
#define NODE_STAGE_STRIDE 4224
#define NODE_SMEM_FLOATS (NODE_STAGE_BASE + 8 * NODE_STAGE_STRIDE)
#define NODE_SMEM_BYTES (NODE_SMEM_FLOATS * 4)

__global__ void __launch_bounds__(256, 1) node_kernel(
    const float* __restrict__ h,
    const float* __restrict__ Wn1, const float* __restrict__ bn1,
    const float* __restrict__ Wn2, const float* __restrict__ bn2,
    float* __restrict__ out_h, float* __restrict__ out_c)
{
    extern __shared__ float s[];
    const int tid = threadIdx.x;
    for (int i = tid; i < 8192; i += 256) s[i]         = Wn1[i];
    for (int i = tid; i < 64;   i += 256) s[8192 + i]  = bn1[i];
    for (int i = tid; i < 4096; i += 256) s[8256 + i]  = Wn2[i];
    for (int i = tid; i < 64;   i += 256) s[12352 + i] = bn2[i];
    __syncthreads();

    const int warp = tid >> 5, lane = tid & 31;
    float* stage = s + NODE_STAGE_BASE + warp * NODE_STAGE_STRIDE;

    const int nbase = blockIdx.x * 256 + warp * 32;
    const int n = nbase + lane;

    #pragma unroll 4
    for (int r = 0; r < 32; r++) {
        const int nr = nbase + r;
        if (nr < NN) {
            const float* hp = h + (size_t)nr * 64;
            const float* ap = g_agg + (size_t)nr * 64;
            stage[(lane)      * 33 + r] = hp[lane];
            stage[(lane + 32) * 33 + r] = hp[lane + 32];
            stage[(lane + 64) * 33 + r] = ap[lane];
            stage[(lane + 96) * 33 + r] = ap[lane + 32];
        } else {
            stage[(lane)      * 33 + r] = 0.f;
            stage[(lane + 32) * 33 + r] = 0.f;
            stage[(lane + 64) * 33 + r] = 0.f;
            stage[(lane + 96) * 33 + r] = 0.f;
        }
    }
    __syncwarp();

    uint64_t acc2[32];
    float m[64];

    {
        const uint64_t* b2 = (const uint64_t*)(s + 8192);
        #pragma unroll
        for (int t = 0; t < 32; t++) acc2[t] = b2[t];
    }
    for (int k = 0; k < 128; k++) {
        const float x = stage[k * 33 + lane];
        const uint64_t xx = pack2(x, x);
        const ulonglong2* w = (const ulonglong2*)(s + k * 64);
        #pragma unroll
        for (int t = 0; t < 16; t++) {
            ulonglong2 wv = w[t];
            fma2(acc2[2 * t + 0], xx, wv.x);
            fma2(acc2[2 * t + 1], xx, wv.y);
        }
    }
    #pragma unroll
    for (int t = 0; t < 32; t++) {
        float a, b; unpack2(acc2[t], a, b);
        m[2 * t + 0] = fmaxf(a, 0.f);
        m[2 * t + 1] = fmaxf(b, 0.f);
    }

    {
        const uint64_t* b2 = (const uint64_t*)(s + 12352);
        #pragma unroll
        for (int t = 0; t < 32; t++) acc2[t] = b2[t];
    }
    #pragma unroll
    for (int k = 0; k < 64; k++) {
        const uint64_t xx = pack2(m[k], m[k]);
        const ulonglong2* w = (const ulonglong2*)(s + 8256 + k * 64);
        #pragma unroll
        for (int t = 0; t < 16; t++) {
            ulonglong2 wv = w[t];
            fma2(acc2[2 * t + 0], xx, wv.x);
            fma2(acc2[2 * t + 1], xx, wv.y);
        }
    }

    if (n < NN) {
        float* op = out_h + (size_t)n * 64;
        #pragma unroll
        for (int t = 0; t < 16; t++) {
            float a, b, c, d;
            unpack2(acc2[2 * t + 0], a, b);
            unpack2(acc2[2 * t + 1], c, d);
            float4 v;
            v.x = stage[(4 * t + 0) * 33 + lane] + a;
            v.y = stage[(4 * t + 1) * 33 + lane] + b;
            v.z = stage[(4 * t + 2) * 33 + lane] + c;
            v.w = stage[(4 * t + 3) * 33 + lane] + d;
            *(float4*)(op + 4 * t) = v;
        }
        const float inv = 1.f / fmaxf(g_cnt[n], 1.f);
        out_c[n * 3 + 0] = g_trans[n * 3 + 0] * inv;
        out_c[n * 3 + 1] = g_trans[n * 3 + 1] * inv;
        out_c[n * 3 + 2] = g_trans[n * 3 + 2] * inv;
    }
}

// ---------------- launch ----------------
extern "C" void kernel_launch(void* const* d_in, const int* in_sizes, int n_in,
                              void* d_out, int out_size)
{
    const float* h     = (const float*)d_in[0];
    const float* coord = (const float*)d_in[1];
    const int*   ei    = (const int*)  d_in[2];
    const float* We1 = (const float*)d_in[3];
    const float* be1 = (const float*)d_in[4];
    const float* We2 = (const float*)d_in[5];
    const float* be2 = (const float*)d_in[6];
    const float* Wn1 = (const float*)d_in[7];
    const float* bn1 = (const float*)d_in[8];
    const float* Wn2 = (const float*)d_in[9];
    const float* bn2 = (const float*)d_in[10];
    const float* Wc1 = (const float*)d_in[11];
    const float* bc1 = (const float*)d_in[12];
    const float* Wc2 = (const float*)d_in[13];

    float* out_h = (float*)d_out;                   // [N, 64]
    float* out_c = (float*)d_out + (size_t)NN * DD; // [N, 3]

    cudaFuncSetAttribute(pq_kernel,   cudaFuncAttributeMaxDynamicSharedMemorySize, PQ_SMEM_BYTES);
    cudaFuncSetAttribute(edge_kernel, cudaFuncAttributeMaxDynamicSharedMemorySize, EDGE_SMEM_BYTES);
    cudaFuncSetAttribute(node_kernel, cudaFuncAttributeMaxDynamicSharedMemorySize, NODE_SMEM_BYTES);

    zero_kernel<<<1024, 256>>>();
    pq_kernel<<<(NN + 255) / 256, 256, PQ_SMEM_BYTES>>>(h, We1, be1);
    edge_kernel<<<444, 128, EDGE_SMEM_BYTES>>>(coord, ei, We1, We2, Wc1, be2, bc1, Wc2);
    node_kernel<<<(NN + 255) / 256, 256, NODE_SMEM_BYTES>>>(h, Wn1, bn1, Wn2, bn2,
                                                            out_h, out_c);
}

// round 9
// speedup vs baseline: 1.1841x; 1.0412x over previous
#include <cuda_runtime.h>
#include <cuda_bf16.h>
#include <mma.h>
#include <cstdint>

using namespace nvcuda;

#define NN 50000
#define EE 1000000
#define DD 64
#define NWT (EE / 16)    // 62500 warp-tiles of 16 edges, exact

// ---------------- scratch (device globals; no allocation allowed) ----------------
__device__ float g_agg[NN * DD];
__device__ float g_trans[NN * 3];
__device__ float g_cnt[NN];
__device__ float g_P[NN * DD];       // h @ We1[0:64] + be1
__device__ float g_Q[NN * DD];       // h @ We1[64:128]

__device__ __forceinline__ void red4(float* p, float a, float b, float c, float d) {
    asm volatile("red.global.add.v4.f32 [%0], {%1, %2, %3, %4};"
                 :: "l"(p), "f"(a), "f"(b), "f"(c), "f"(d) : "memory");
}
__device__ __forceinline__ uint64_t pack2(float x, float y) {
    uint64_t r; asm("mov.b64 %0, {%1, %2};" : "=l"(r) : "f"(x), "f"(y)); return r;
}
__device__ __forceinline__ void unpack2(uint64_t v, float& x, float& y) {
    asm("mov.b64 {%0, %1}, %2;" : "=f"(x), "=f"(y) : "l"(v));
}
__device__ __forceinline__ void fma2(uint64_t& acc, uint64_t a, uint64_t b) {
    asm("fma.rn.f32x2 %0, %1, %2, %0;" : "+l"(acc) : "l"(a), "l"(b));
}
__device__ __forceinline__ uint32_t bf2u(__nv_bfloat162 v) {
    uint32_t u; memcpy(&u, &v, 4); return u;
}

// ---------------- zero scratch ----------------
__global__ void zero_kernel() {
    int i = blockIdx.x * blockDim.x + threadIdx.x;
    int stride = gridDim.x * blockDim.x;
    for (int j = i; j < NN * DD; j += stride) g_agg[j] = 0.f;
    for (int j = i; j < NN * 3;  j += stride) g_trans[j] = 0.f;
    for (int j = i; j < NN;      j += stride) g_cnt[j] = 0.f;
}

// ---------------- pq kernel (unchanged) ----------------
#define PQ_STAGE_BASE 8256
#define PQ_STAGE_STRIDE 2112
#define PQ_SMEM_FLOATS (PQ_STAGE_BASE + 8 * PQ_STAGE_STRIDE)
#define PQ_SMEM_BYTES (PQ_SMEM_FLOATS * 4)

__global__ void __launch_bounds__(256, 1) pq_kernel(
    const float* __restrict__ h,
    const float* __restrict__ We1, const float* __restrict__ be1)
{
    extern __shared__ float s[];
    const int tid = threadIdx.x;
    for (int i = tid; i < 8192; i += 256) s[i] = We1[i];
    for (int i = tid; i < 64;   i += 256) s[8192 + i] = be1[i];
    __syncthreads();

    const int warp = tid >> 5, lane = tid & 31;
    float* stage = s + PQ_STAGE_BASE + warp * PQ_STAGE_STRIDE;
    const int nbase = blockIdx.x * 256 + warp * 32;
    const int n = nbase + lane;

    #pragma unroll 4
    for (int r = 0; r < 32; r++) {
        const int nr = nbase + r;
        if (nr < NN) {
            const float* hp = h + (size_t)nr * 64;
            stage[lane * 33 + r]        = hp[lane];
            stage[(lane + 32) * 33 + r] = hp[lane + 32];
        } else {
            stage[lane * 33 + r]        = 0.f;
            stage[(lane + 32) * 33 + r] = 0.f;
        }
    }
    __syncwarp();

    uint64_t acc2[32];
    {
        const uint64_t* b2 = (const uint64_t*)(s + 8192);
        #pragma unroll
        for (int t = 0; t < 32; t++) acc2[t] = b2[t];
    }
    for (int k = 0; k < 64; k++) {
        const float x = stage[k * 33 + lane];
        const uint64_t xx = pack2(x, x);
        const ulonglong2* w = (const ulonglong2*)(s + k * 64);
        #pragma unroll
        for (int t = 0; t < 16; t++) {
            ulonglong2 wv = w[t];
            fma2(acc2[2 * t + 0], xx, wv.x);
            fma2(acc2[2 * t + 1], xx, wv.y);
        }
    }
    if (n < NN) {
        float* op = g_P + (size_t)n * 64;
        #pragma unroll
        for (int t = 0; t < 16; t++) {
            float a, b, c, d;
            unpack2(acc2[2 * t + 0], a, b);
            unpack2(acc2[2 * t + 1], c, d);
            float4 v; v.x = a; v.y = b; v.z = c; v.w = d;
            *(float4*)(op + 4 * t) = v;
        }
    }

    #pragma unroll
    for (int t = 0; t < 32; t++) acc2[t] = 0ull;
    for (int k = 0; k < 64; k++) {
        const float x = stage[k * 33 + lane];
        const uint64_t xx = pack2(x, x);
        const ulonglong2* w = (const ulonglong2*)(s + (64 + k) * 64);
        #pragma unroll
        for (int t = 0; t < 16; t++) {
            ulonglong2 wv = w[t];
            fma2(acc2[2 * t + 0], xx, wv.x);
            fma2(acc2[2 * t + 1], xx, wv.y);
        }
    }
    if (n < NN) {
        float* op = g_Q + (size_t)n * 64;
        #pragma unroll
        for (int t = 0; t < 16; t++) {
            float a, b, c, d;
            unpack2(acc2[2 * t + 0], a, b);
            unpack2(acc2[2 * t + 1], c, d);
            float4 v; v.x = a; v.y = b; v.z = c; v.w = d;
            *(float4*)(op + 4 * t) = v;
        }
    }
}

// ---------------- edge kernel: warp-autonomous 16-edge tiles ----------------
// 128 threads/CTA, 3 CTAs/SM. NO CTA barriers inside the tile loop.
// SMEM byte map:
//   floats s[]: w128 @0, be2 @64, bc1 @128, wc2 @192
//   bf16 W tiles (stride 72): WE2H @4096, WE2L @13312, WC1H @22528, WC1L @31744
//   A/D per-warp blocks @40960, 4 x 4736 B: [hi 16x72 | lo 16x72 | pad]
//     D (f32 16x68) overlays block start after each GEMM
#define EB_WE2H 4096
#define EB_WE2L 13312
#define EB_WC1H 22528
#define EB_WC1L 31744
#define EB_A    40960
#define AB_STRIDE 4736
#define AB_LO   2304
#define EDGE_SMEM_BYTES 59904

__device__ __forceinline__ void gemm_hilo(char* sc, int whOff, int wlOff, char* ab) {
    wmma::fragment<wmma::accumulator, 16, 16, 16, float> acc[4];
    #pragma unroll
    for (int ct = 0; ct < 4; ct++) wmma::fill_fragment(acc[ct], 0.f);

    const __nv_bfloat16* Ah = (const __nv_bfloat16*)(ab);
    const __nv_bfloat16* Al = (const __nv_bfloat16*)(ab + AB_LO);
    const __nv_bfloat16* Wh = (const __nv_bfloat16*)(sc + whOff);
    const __nv_bfloat16* Wl = (const __nv_bfloat16*)(sc + wlOff);

    #pragma unroll
    for (int k0 = 0; k0 < 4; k0++) {
        wmma::fragment<wmma::matrix_a, 16, 16, 16, __nv_bfloat16, wmma::row_major> a_h, a_l;
        wmma::load_matrix_sync(a_h, Ah + k0 * 16, 72);
        wmma::load_matrix_sync(a_l, Al + k0 * 16, 72);
        #pragma unroll
        for (int ct = 0; ct < 4; ct++) {
            wmma::fragment<wmma::matrix_b, 16, 16, 16, __nv_bfloat16, wmma::row_major> b_h, b_l;
            wmma::load_matrix_sync(b_h, Wh + k0 * 16 * 72 + ct * 16, 72);
            wmma::load_matrix_sync(b_l, Wl + k0 * 16 * 72 + ct * 16, 72);
            wmma::mma_sync(acc[ct], a_h, b_h, acc[ct]);
            wmma::mma_sync(acc[ct], a_l, b_h, acc[ct]);
            wmma::mma_sync(acc[ct], a_h, b_l, acc[ct]);
        }
    }
    float* Dp = (float*)ab;     // D overlays this warp's own A block
    #pragma unroll
    for (int ct = 0; ct < 4; ct++)
        wmma::store_matrix_sync(Dp + ct * 16, acc[ct], 68, wmma::mem_row_major);
}

__global__ void __launch_bounds__(128, 3) edge_kernel(
    const float* __restrict__ coord,
    const int* __restrict__ ei,
    const float* __restrict__ We1,   // row 128 only
    const float* __restrict__ We2,
    const float* __restrict__ Wc1, const float* __restrict__ be2,
    const float* __restrict__ bc1, const float* __restrict__ Wc2)
{
    extern __shared__ __align__(16) char sc[];
    float* s = (float*)sc;

    const int tid = threadIdx.x;
    const int wid = tid >> 5, lane = tid & 31;

    // scalars
    for (int i = tid; i < 64; i += 128) {
        s[i]        = We1[128 * 64 + i];
        s[64 + i]   = be2[i];
        s[128 + i]  = bc1[i];
        s[192 + i]  = Wc2[i];
    }
    // weight tiles: [k][n] row-major, stride 72, hi/lo bf16
    for (int i = tid; i < 4096; i += 128) {
        const int k = i >> 6, n = i & 63;
        {
            float v = We2[i];
            __nv_bfloat16 hb = __float2bfloat16(v);
            __nv_bfloat16 lb = __float2bfloat16(v - __bfloat162float(hb));
            ((__nv_bfloat16*)(sc + EB_WE2H))[k * 72 + n] = hb;
            ((__nv_bfloat16*)(sc + EB_WE2L))[k * 72 + n] = lb;
        }
        {
            float v = Wc1[i];
            __nv_bfloat16 hb = __float2bfloat16(v);
            __nv_bfloat16 lb = __float2bfloat16(v - __bfloat162float(hb));
            ((__nv_bfloat16*)(sc + EB_WC1H))[k * 72 + n] = hb;
            ((__nv_bfloat16*)(sc + EB_WC1L))[k * 72 + n] = lb;
        }
    }
    __syncthreads();   // weights ready; no more CTA barriers

    const int r = lane >> 1;         // edge row within warp tile (0..15)
    const int hh = lane & 1;         // column half
    const int c0 = hh * 32;
    char* ab = sc + EB_A + wid * AB_STRIDE;
    const unsigned FULL = 0xFFFFFFFFu;

    const int gw = blockIdx.x * 4 + wid;
    const int nw = gridDim.x * 4;

    for (int wt = gw; wt < NWT; wt += nw) {
        // lanes 0..15 each load one edge
        int row = 0, col = 0; float dx = 0.f, dy = 0.f, dz = 0.f, rad = 0.f;
        if (lane < 16) {
            const int e = wt * 16 + lane;
            row = ei[e];
            col = ei[EE + e];
            dx = coord[row * 3 + 0] - coord[col * 3 + 0];
            dy = coord[row * 3 + 1] - coord[col * 3 + 1];
            dz = coord[row * 3 + 2] - coord[col * 3 + 2];
            rad = dx * dx + dy * dy + dz * dz;
        }
        const int myrow = __shfl_sync(FULL, row, r);
        const int mycol = __shfl_sync(FULL, col, r);
        const float myrad = __shfl_sync(FULL, rad, r);

        // ---- build A1 = relu(P[row]+Q[col]+rad*w128) hi/lo ----
        {
            const float4* Pp = (const float4*)(g_P + (size_t)myrow * 64 + c0);
            const float4* Qp = (const float4*)(g_Q + (size_t)mycol * 64 + c0);
            const float4* wp = (const float4*)(s + c0);
            uint2* ah = (uint2*)(ab + r * 144 + hh * 64);
            uint2* al = (uint2*)(ab + AB_LO + r * 144 + hh * 64);
            #pragma unroll
            for (int j = 0; j < 8; j++) {
                float4 p = Pp[j], q = Qp[j], w = wp[j];
                const float v0 = fmaxf(fmaf(myrad, w.x, p.x + q.x), 0.f);
                const float v1 = fmaxf(fmaf(myrad, w.y, p.y + q.y), 0.f);
                const float v2 = fmaxf(fmaf(myrad, w.z, p.z + q.z), 0.f);
                const float v3 = fmaxf(fmaf(myrad, w.w, p.w + q.w), 0.f);
                __nv_bfloat162 h01 = __floats2bfloat162_rn(v0, v1);
                __nv_bfloat162 h23 = __floats2bfloat162_rn(v2, v3);
                __nv_bfloat162 l01 = __floats2bfloat162_rn(v0 - __bfloat162float(h01.x),
                                                           v1 - __bfloat162float(h01.y));
                __nv_bfloat162 l23 = __floats2bfloat162_rn(v2 - __bfloat162float(h23.x),
                                                           v3 - __bfloat162float(h23.y));
                ah[j] = make_uint2(bf2u(h01), bf2u(h23));
                al[j] = make_uint2(bf2u(l01), bf2u(l23));
            }
        }
        __syncwarp();

        // ---- GEMM1 (warp-local): D = A1 @ We2, D overlays A1 ----
        gemm_hilo(sc, EB_WE2H, EB_WE2L, ab);
        __syncwarp();

        // ---- epilogue 1: ef = relu(D + be2); scatter; rebuild A2 ----
        float ef[32];
        {
            const float4* Dr = (const float4*)((float*)ab + r * 68 + c0);
            const float4* bb = (const float4*)(s + 64 + c0);
            #pragma unroll
            for (int j = 0; j < 8; j++) {
                float4 d = Dr[j], b = bb[j];
                ef[4 * j + 0] = fmaxf(d.x + b.x, 0.f);
                ef[4 * j + 1] = fmaxf(d.y + b.y, 0.f);
                ef[4 * j + 2] = fmaxf(d.z + b.z, 0.f);
                ef[4 * j + 3] = fmaxf(d.w + b.w, 0.f);
            }
        }
        __syncwarp();   // D reads complete before A2 overwrites

        {
            float* dst = g_agg + (size_t)myrow * 64 + c0;
            #pragma unroll
            for (int j = 0; j < 8; j++)
                red4(dst + 4 * j, ef[4 * j], ef[4 * j + 1], ef[4 * j + 2], ef[4 * j + 3]);

            uint2* ah = (uint2*)(ab + r * 144 + hh * 64);
            uint2* al = (uint2*)(ab + AB_LO + r * 144 + hh * 64);
            #pragma unroll
            for (int j = 0; j < 8; j++) {
                const float v0 = ef[4 * j + 0], v1 = ef[4 * j + 1];
                const float v2 = ef[4 * j + 2], v3 = ef[4 * j + 3];
                __nv_bfloat162 h01 = __floats2bfloat162_rn(v0, v1);
                __nv_bfloat162 h23 = __floats2bfloat162_rn(v2, v3);
                __nv_bfloat162 l01 = __floats2bfloat162_rn(v0 - __bfloat162float(h01.x),
                                                           v1 - __bfloat162float(h01.y));
                __nv_bfloat162 l23 = __floats2bfloat162_rn(v2 - __bfloat162float(h23.x),
                                                           v3 - __bfloat162float(h23.y));
                ah[j] = make_uint2(bf2u(h01), bf2u(h23));
                al[j] = make_uint2(bf2u(l01), bf2u(l23));
            }
        }
        __syncwarp();

        // ---- GEMM2 (warp-local): D = EF @ Wc1 ----
        gemm_hilo(sc, EB_WC1H, EB_WC1L, ab);
        __syncwarp();

        // ---- epilogue 2: gate -> coord atomics ----
        {
            const float4* Dr = (const float4*)((float*)ab + r * 68 + c0);
            const float4* bb = (const float4*)(s + 128 + c0);
            const float4* wc = (const float4*)(s + 192 + c0);
            float g = 0.f;
            #pragma unroll
            for (int j = 0; j < 8; j++) {
                float4 d = Dr[j], b = bb[j], w = wc[j];
                g += fmaxf(d.x + b.x, 0.f) * w.x;
                g += fmaxf(d.y + b.y, 0.f) * w.y;
                g += fmaxf(d.z + b.z, 0.f) * w.z;
                g += fmaxf(d.w + b.w, 0.f) * w.w;
            }
            g += __shfl_xor_sync(FULL, g, 1);
            const float dxr = __shfl_sync(FULL, dx, r);
            const float dyr = __shfl_sync(FULL, dy, r);
            const float dzr = __shfl_sync(FULL, dz, r);
            if (hh == 0) {
                const float tx = fminf(fmaxf(dxr * g, -100.f), 100.f);
                const float ty = fminf(fmaxf(dyr * g, -100.f), 100.f);
                const float tz = fminf(fmaxf(dzr * g, -100.f), 100.f);
                atomicAdd(&g_trans[myrow * 3 + 0], tx);
                atomicAdd(&g_trans[myrow * 3 + 1], ty);
                atomicAdd(&g_trans[myrow * 3 + 2], tz);
                atomicAdd(&g_cnt[myrow], 1.f);
            }
        }
        __syncwarp();
    }
}

// ---------------- node kernel (unchanged) ----------------
#define NODE_STAGE_BASE 12416
#define NODE_STAGE_STRIDE 4224
#define NODE_SMEM_FLOATS (NODE_STAGE_BASE + 8 * NODE_STAGE_STRIDE)
#define NODE_SMEM_BYTES (NODE_SMEM_FLOATS * 4)

__global__ void __launch_bounds__(256, 1) node_kernel(
    const float* __restrict__ h,
    const float* __restrict__ Wn1, const float* __restrict__ bn1,
    const float* __restrict__ Wn2, const float* __restrict__ bn2,
    float* __restrict__ out_h, float* __restrict__ out_c)
{
    extern __shared__ float s[];
    const int tid = threadIdx.x;
    for (int i = tid; i < 8192; i += 256) s[i]         = Wn1[i];
    for (int i = tid; i < 64;   i += 256) s[8192 + i]  = bn1[i];
    for (int i = tid; i < 4096; i += 256) s[8256 + i]  = Wn2[i];
    for (int i = tid; i < 64;   i += 256) s[12352 + i] = bn2[i];
    __syncthreads();

    const int warp = tid >> 5, lane = tid & 31;
    float* stage = s + NODE_STAGE_BASE + warp * NODE_STAGE_STRIDE;

    const int nbase = blockIdx.x * 256 + warp * 32;
    const int n = nbase + lane;

    #pragma unroll 4
    for (int r = 0; r < 32; r++) {
        const int nr = nbase + r;
        if (nr < NN) {
            const float* hp = h + (size_t)nr * 64;
            const float* ap = g_agg + (size_t)nr * 64;
            stage[(lane)      * 33 + r] = hp[lane];
            stage[(lane + 32) * 33 + r] = hp[lane + 32];
            stage[(lane + 64) * 33 + r] = ap[lane];
            stage[(lane + 96) * 33 + r] = ap[lane + 32];
        } else {
            stage[(lane)      * 33 + r] = 0.f;
            stage[(lane + 32) * 33 + r] = 0.f;
            stage[(lane + 64) * 33 + r] = 0.f;
            stage[(lane + 96) * 33 + r] = 0.f;
        }
    }
    __syncwarp();

    uint64_t acc2[32];
    float m[64];

    {
        const uint64_t* b2 = (const uint64_t*)(s + 8192);
        #pragma unroll
        for (int t = 0; t < 32; t++) acc2[t] = b2[t];
    }
    for (int k = 0; k < 128; k++) {
        const float x = stage[k * 33 + lane];
        const uint64_t xx = pack2(x, x);
        const ulonglong2* w = (const ulonglong2*)(s + k * 64);
        #pragma unroll
        for (int t = 0; t < 16; t++) {
            ulonglong2 wv = w[t];
            fma2(acc2[2 * t + 0], xx, wv.x);
            fma2(acc2[2 * t + 1], xx, wv.y);
        }
    }
    #pragma unroll
    for (int t = 0; t < 32; t++) {
        float a, b; unpack2(acc2[t], a, b);
        m[2 * t + 0] = fmaxf(a, 0.f);
        m[2 * t + 1] = fmaxf(b, 0.f);
    }

    {
        const uint64_t* b2 = (const uint64_t*)(s + 12352);
        #pragma unroll
        for (int t = 0; t < 32; t++) acc2[t] = b2[t];
    }
    #pragma unroll
    for (int k = 0; k < 64; k++) {
        const uint64_t xx = pack2(m[k], m[k]);
        const ulonglong2* w = (const ulonglong2*)(s + 8256 + k * 64);
        #pragma unroll
        for (int t = 0; t < 16; t++) {
            ulonglong2 wv = w[t];
            fma2(acc2[2 * t + 0], xx, wv.x);
            fma2(acc2[2 * t + 1], xx, wv.y);
        }
    }

    if (n < NN) {
        float* op = out_h + (size_t)n * 64;
        #pragma unroll
        for (int t = 0; t < 16; t++) {
            float a, b, c, d;
            unpack2(acc2[2 * t + 0], a, b);
            unpack2(acc2[2 * t + 1], c, d);
            float4 v;
            v.x = stage[(4 * t + 0) * 33 + lane] + a;
            v.y = stage[(4 * t + 1) * 33 + lane] + b;
            v.z = stage[(4 * t + 2) * 33 + lane] + c;
            v.w = stage[(4 * t + 3) * 33 + lane] + d;
            *(float4*)(op + 4 * t) = v;
        }
        const float inv = 1.f / fmaxf(g_cnt[n], 1.f);
        out_c[n * 3 + 0] = g_trans[n * 3 + 0] * inv;
        out_c[n * 3 + 1] = g_trans[n * 3 + 1] * inv;
        out_c[n * 3 + 2] = g_trans[n * 3 + 2] * inv;
    }
}

// ---------------- launch ----------------
extern "C" void kernel_launch(void* const* d_in, const int* in_sizes, int n_in,
                              void* d_out, int out_size)
{
    const float* h     = (const float*)d_in[0];
    const float* coord = (const float*)d_in[1];
    const int*   ei    = (const int*)  d_in[2];
    const float* We1 = (const float*)d_in[3];
    const float* be1 = (const float*)d_in[4];
    const float* We2 = (const float*)d_in[5];
    const float* be2 = (const float*)d_in[6];
    const float* Wn1 = (const float*)d_in[7];
    const float* bn1 = (const float*)d_in[8];
    const float* Wn2 = (const float*)d_in[9];
    const float* bn2 = (const float*)d_in[10];
    const float* Wc1 = (const float*)d_in[11];
    const float* bc1 = (const float*)d_in[12];
    const float* Wc2 = (const float*)d_in[13];

    float* out_h = (float*)d_out;                   // [N, 64]
    float* out_c = (float*)d_out + (size_t)NN * DD; // [N, 3]

    cudaFuncSetAttribute(pq_kernel,   cudaFuncAttributeMaxDynamicSharedMemorySize, PQ_SMEM_BYTES);
    cudaFuncSetAttribute(edge_kernel, cudaFuncAttributeMaxDynamicSharedMemorySize, EDGE_SMEM_BYTES);
    cudaFuncSetAttribute(node_kernel, cudaFuncAttributeMaxDynamicSharedMemorySize, NODE_SMEM_BYTES);

    zero_kernel<<<1024, 256>>>();
    pq_kernel<<<(NN + 255) / 256, 256, PQ_SMEM_BYTES>>>(h, We1, be1);
    edge_kernel<<<444, 128, EDGE_SMEM_BYTES>>>(coord, ei, We1, We2, Wc1, be2, bc1, Wc2);
    node_kernel<<<(NN + 255) / 256, 256, NODE_SMEM_BYTES>>>(h, Wn1, bn1, Wn2, bn2,
                                                            out_h, out_c);
}

// round 10
// speedup vs baseline: 1.5839x; 1.3376x over previous
#include <cuda_runtime.h>
#include <cuda_bf16.h>
#include <mma.h>
#include <cstdint>

using namespace nvcuda;

#define NN 50000
#define EE 1000000
#define DD 64
#define NWT (EE / 16)    // 62500 warp-tiles of 16 edges, exact

// ---------------- scratch (device globals; no allocation allowed) ----------------
__device__ float g_agg[NN * DD];
__device__ float g_trans[NN * 3];
__device__ float g_cnt[NN];
__device__ float g_P[NN * DD];       // h @ We1[0:64] + be1
__device__ float g_Q[NN * DD];       // h @ We1[64:128]

__device__ __forceinline__ void red2(float* p, float a, float b) {
    asm volatile("red.global.add.v2.f32 [%0], {%1, %2};"
                 :: "l"(p), "f"(a), "f"(b) : "memory");
}
__device__ __forceinline__ uint64_t pack2(float x, float y) {
    uint64_t r; asm("mov.b64 %0, {%1, %2};" : "=l"(r) : "f"(x), "f"(y)); return r;
}
__device__ __forceinline__ void unpack2(uint64_t v, float& x, float& y) {
    asm("mov.b64 {%0, %1}, %2;" : "=f"(x), "=f"(y) : "l"(v));
}
__device__ __forceinline__ void fma2(uint64_t& acc, uint64_t a, uint64_t b) {
    asm("fma.rn.f32x2 %0, %1, %2, %0;" : "+l"(acc) : "l"(a), "l"(b));
}
__device__ __forceinline__ uint32_t bf2u(__nv_bfloat162 v) {
    uint32_t u; memcpy(&u, &v, 4); return u;
}

// ---------------- zero scratch ----------------
__global__ void zero_kernel() {
    int i = blockIdx.x * blockDim.x + threadIdx.x;
    int stride = gridDim.x * blockDim.x;
    for (int j = i; j < NN * DD; j += stride) g_agg[j] = 0.f;
    for (int j = i; j < NN * 3;  j += stride) g_trans[j] = 0.f;
    for (int j = i; j < NN;      j += stride) g_cnt[j] = 0.f;
}

// ---------------- pq kernel (unchanged) ----------------
#define PQ_STAGE_BASE 8256
#define PQ_STAGE_STRIDE 2112
#define PQ_SMEM_FLOATS (PQ_STAGE_BASE + 8 * PQ_STAGE_STRIDE)
#define PQ_SMEM_BYTES (PQ_SMEM_FLOATS * 4)

__global__ void __launch_bounds__(256, 1) pq_kernel(
    const float* __restrict__ h,
    const float* __restrict__ We1, const float* __restrict__ be1)
{
    extern __shared__ float s[];
    const int tid = threadIdx.x;
    for (int i = tid; i < 8192; i += 256) s[i] = We1[i];
    for (int i = tid; i < 64;   i += 256) s[8192 + i] = be1[i];
    __syncthreads();

    const int warp = tid >> 5, lane = tid & 31;
    float* stage = s + PQ_STAGE_BASE + warp * PQ_STAGE_STRIDE;
    const int nbase = blockIdx.x * 256 + warp * 32;
    const int n = nbase + lane;

    #pragma unroll 4
    for (int r = 0; r < 32; r++) {
        const int nr = nbase + r;
        if (nr < NN) {
            const float* hp = h + (size_t)nr * 64;
            stage[lane * 33 + r]        = hp[lane];
            stage[(lane + 32) * 33 + r] = hp[lane + 32];
        } else {
            stage[lane * 33 + r]        = 0.f;
            stage[(lane + 32) * 33 + r] = 0.f;
        }
    }
    __syncwarp();

    uint64_t acc2[32];
    {
        const uint64_t* b2 = (const uint64_t*)(s + 8192);
        #pragma unroll
        for (int t = 0; t < 32; t++) acc2[t] = b2[t];
    }
    for (int k = 0; k < 64; k++) {
        const float x = stage[k * 33 + lane];
        const uint64_t xx = pack2(x, x);
        const ulonglong2* w = (const ulonglong2*)(s + k * 64);
        #pragma unroll
        for (int t = 0; t < 16; t++) {
            ulonglong2 wv = w[t];
            fma2(acc2[2 * t + 0], xx, wv.x);
            fma2(acc2[2 * t + 1], xx, wv.y);
        }
    }
    if (n < NN) {
        float* op = g_P + (size_t)n * 64;
        #pragma unroll
        for (int t = 0; t < 16; t++) {
            float a, b, c, d;
            unpack2(acc2[2 * t + 0], a, b);
            unpack2(acc2[2 * t + 1], c, d);
            float4 v; v.x = a; v.y = b; v.z = c; v.w = d;
            *(float4*)(op + 4 * t) = v;
        }
    }

    #pragma unroll
    for (int t = 0; t < 32; t++) acc2[t] = 0ull;
    for (int k = 0; k < 64; k++) {
        const float x = stage[k * 33 + lane];
        const uint64_t xx = pack2(x, x);
        const ulonglong2* w = (const ulonglong2*)(s + (64 + k) * 64);
        #pragma unroll
        for (int t = 0; t < 16; t++) {
            ulonglong2 wv = w[t];
            fma2(acc2[2 * t + 0], xx, wv.x);
            fma2(acc2[2 * t + 1], xx, wv.y);
        }
    }
    if (n < NN) {
        float* op = g_Q + (size_t)n * 64;
        #pragma unroll
        for (int t = 0; t < 16; t++) {
            float a, b, c, d;
            unpack2(acc2[2 * t + 0], a, b);
            unpack2(acc2[2 * t + 1], c, d);
            float4 v; v.x = a; v.y = b; v.z = c; v.w = d;
            *(float4*)(op + 4 * t) = v;
        }
    }
}

// ---------------- edge kernel: warp-autonomous, fully coalesced gather/scatter ----------------
// 128 threads/CTA, 3 CTAs/SM. No CTA barriers in the tile loop.
// SMEM byte map:
//   floats s[]: w128 @0, be2 @64, bc1 @128, wc2 @192
//   bf16 W tiles (stride 72): WE2H @4096, WE2L @13312, WC1H @22528, WC1L @31744
//   per-warp blocks @40960, 4 x 8960 B: [D f32 16x68 = 4352 | Ah 16x72 bf16 = 2304 | Al 2304]
#define EB_WE2H 4096
#define EB_WE2L 13312
#define EB_WC1H 22528
#define EB_WC1L 31744
#define EB_BLK  40960
#define BLK_STRIDE 8960
#define BLK_AH 4352
#define BLK_AL 6656
#define EDGE_SMEM_BYTES (EB_BLK + 4 * BLK_STRIDE)   // 76800

__device__ __forceinline__ void gemm_hilo(char* sc, int whOff, int wlOff, char* ab) {
    wmma::fragment<wmma::accumulator, 16, 16, 16, float> acc[4];
    #pragma unroll
    for (int ct = 0; ct < 4; ct++) wmma::fill_fragment(acc[ct], 0.f);

    const __nv_bfloat16* Ah = (const __nv_bfloat16*)(ab + BLK_AH);
    const __nv_bfloat16* Al = (const __nv_bfloat16*)(ab + BLK_AL);
    const __nv_bfloat16* Wh = (const __nv_bfloat16*)(sc + whOff);
    const __nv_bfloat16* Wl = (const __nv_bfloat16*)(sc + wlOff);

    #pragma unroll
    for (int k0 = 0; k0 < 4; k0++) {
        wmma::fragment<wmma::matrix_a, 16, 16, 16, __nv_bfloat16, wmma::row_major> a_h, a_l;
        wmma::load_matrix_sync(a_h, Ah + k0 * 16, 72);
        wmma::load_matrix_sync(a_l, Al + k0 * 16, 72);
        #pragma unroll
        for (int ct = 0; ct < 4; ct++) {
            wmma::fragment<wmma::matrix_b, 16, 16, 16, __nv_bfloat16, wmma::row_major> b_h, b_l;
            wmma::load_matrix_sync(b_h, Wh + k0 * 16 * 72 + ct * 16, 72);
            wmma::load_matrix_sync(b_l, Wl + k0 * 16 * 72 + ct * 16, 72);
            wmma::mma_sync(acc[ct], a_h, b_h, acc[ct]);
            wmma::mma_sync(acc[ct], a_l, b_h, acc[ct]);
            wmma::mma_sync(acc[ct], a_h, b_l, acc[ct]);
        }
    }
    float* Dp = (float*)ab;   // D region is disjoint from A
    #pragma unroll
    for (int ct = 0; ct < 4; ct++)
        wmma::store_matrix_sync(Dp + ct * 16, acc[ct], 68, wmma::mem_row_major);
}

__global__ void __launch_bounds__(128, 3) edge_kernel(
    const float* __restrict__ coord,
    const int* __restrict__ ei,
    const float* __restrict__ We1,   // row 128 only
    const float* __restrict__ We2,
    const float* __restrict__ Wc1, const float* __restrict__ be2,
    const float* __restrict__ bc1, const float* __restrict__ Wc2)
{
    extern __shared__ __align__(16) char sc[];
    float* s = (float*)sc;

    const int tid = threadIdx.x;
    const int wid = tid >> 5, lane = tid & 31;

    for (int i = tid; i < 64; i += 128) {
        s[i]        = We1[128 * 64 + i];
        s[64 + i]   = be2[i];
        s[128 + i]  = bc1[i];
        s[192 + i]  = Wc2[i];
    }
    for (int i = tid; i < 4096; i += 128) {
        const int k = i >> 6, n = i & 63;
        {
            float v = We2[i];
            __nv_bfloat16 hb = __float2bfloat16(v);
            __nv_bfloat16 lb = __float2bfloat16(v - __bfloat162float(hb));
            ((__nv_bfloat16*)(sc + EB_WE2H))[k * 72 + n] = hb;
            ((__nv_bfloat16*)(sc + EB_WE2L))[k * 72 + n] = lb;
        }
        {
            float v = Wc1[i];
            __nv_bfloat16 hb = __float2bfloat16(v);
            __nv_bfloat16 lb = __float2bfloat16(v - __bfloat162float(hb));
            ((__nv_bfloat16*)(sc + EB_WC1H))[k * 72 + n] = hb;
            ((__nv_bfloat16*)(sc + EB_WC1L))[k * 72 + n] = lb;
        }
    }
    __syncthreads();   // weights ready; no CTA barriers after this

    char* ab = sc + EB_BLK + wid * BLK_STRIDE;
    const unsigned FULL = 0xFFFFFFFFu;

    // per-lane column-pair constants (cols 2*lane, 2*lane+1)
    const float wl0 = s[2 * lane],       wl1 = s[2 * lane + 1];
    const float b20 = s[64 + 2 * lane],  b21 = s[64 + 2 * lane + 1];

    // epilogue-2 mapping: thread (r2, hh) covers row r2, cols c0..c0+31
    const int r2 = lane >> 1;
    const int hh = lane & 1;
    const int c0 = hh * 32;

    const int gw = blockIdx.x * 4 + wid;
    const int nw = gridDim.x * 4;

    for (int wt = gw; wt < NWT; wt += nw) {
        // lanes 0..15 each own one edge
        int row = 0, col = 0; float dx = 0.f, dy = 0.f, dz = 0.f, rad = 0.f;
        if (lane < 16) {
            const int e = wt * 16 + lane;
            row = ei[e];
            col = ei[EE + e];
            dx = coord[row * 3 + 0] - coord[col * 3 + 0];
            dy = coord[row * 3 + 1] - coord[col * 3 + 1];
            dz = coord[row * 3 + 2] - coord[col * 3 + 2];
            rad = dx * dx + dy * dy + dz * dz;
        }

        // ---- staging: coalesced row-at-a-time A1 = relu(P[er]+Q[ec]+rad*w128) ----
        #pragma unroll
        for (int r = 0; r < 16; r++) {
            const int er = __shfl_sync(FULL, row, r);
            const int ec = __shfl_sync(FULL, col, r);
            const float rr = __shfl_sync(FULL, rad, r);
            const float2 p = *(const float2*)(g_P + (size_t)er * 64 + 2 * lane);
            const float2 q = *(const float2*)(g_Q + (size_t)ec * 64 + 2 * lane);
            const float v0 = fmaxf(fmaf(rr, wl0, p.x + q.x), 0.f);
            const float v1 = fmaxf(fmaf(rr, wl1, p.y + q.y), 0.f);
            __nv_bfloat162 hb = __floats2bfloat162_rn(v0, v1);
            __nv_bfloat162 lb = __floats2bfloat162_rn(v0 - __bfloat162float(hb.x),
                                                      v1 - __bfloat162float(hb.y));
            *(uint32_t*)(ab + BLK_AH + r * 144 + lane * 4) = bf2u(hb);
            *(uint32_t*)(ab + BLK_AL + r * 144 + lane * 4) = bf2u(lb);
        }
        __syncwarp();

        // ---- GEMM1 (warp-local): D = A1 @ We2 ----
        gemm_hilo(sc, EB_WE2H, EB_WE2L, ab);
        __syncwarp();

        // ---- epilogue 1: coalesced per-row relu+bias, scatter, rebuild A2 ----
        #pragma unroll
        for (int r = 0; r < 16; r++) {
            const int er = __shfl_sync(FULL, row, r);
            const float2 d = *(const float2*)((float*)ab + r * 68 + 2 * lane);
            const float e0 = fmaxf(d.x + b20, 0.f);
            const float e1 = fmaxf(d.y + b21, 0.f);
            red2(g_agg + (size_t)er * 64 + 2 * lane, e0, e1);
            __nv_bfloat162 hb = __floats2bfloat162_rn(e0, e1);
            __nv_bfloat162 lb = __floats2bfloat162_rn(e0 - __bfloat162float(hb.x),
                                                      e1 - __bfloat162float(hb.y));
            *(uint32_t*)(ab + BLK_AH + r * 144 + lane * 4) = bf2u(hb);
            *(uint32_t*)(ab + BLK_AL + r * 144 + lane * 4) = bf2u(lb);
        }
        __syncwarp();

        // ---- GEMM2 (warp-local): D = EF @ Wc1 ----
        gemm_hilo(sc, EB_WC1H, EB_WC1L, ab);
        __syncwarp();

        // ---- epilogue 2: gate -> coord atomics ----
        {
            const float4* Dr = (const float4*)((float*)ab + r2 * 68 + c0);
            const float4* bb = (const float4*)(s + 128 + c0);
            const float4* wc = (const float4*)(s + 192 + c0);
            float g = 0.f;
            #pragma unroll
            for (int j = 0; j < 8; j++) {
                float4 d = Dr[j], b = bb[j], w = wc[j];
                g += fmaxf(d.x + b.x, 0.f) * w.x;
                g += fmaxf(d.y + b.y, 0.f) * w.y;
                g += fmaxf(d.z + b.z, 0.f) * w.z;
                g += fmaxf(d.w + b.w, 0.f) * w.w;
            }
            g += __shfl_xor_sync(FULL, g, 1);
            const int   mr  = __shfl_sync(FULL, row, r2);
            const float dxr = __shfl_sync(FULL, dx, r2);
            const float dyr = __shfl_sync(FULL, dy, r2);
            const float dzr = __shfl_sync(FULL, dz, r2);
            if (hh == 0) {
                const float tx = fminf(fmaxf(dxr * g, -100.f), 100.f);
                const float ty = fminf(fmaxf(dyr * g, -100.f), 100.f);
                const float tz = fminf(fmaxf(dzr * g, -100.f), 100.f);
                atomicAdd(&g_trans[mr * 3 + 0], tx);
                atomicAdd(&g_trans[mr * 3 + 1], ty);
                atomicAdd(&g_trans[mr * 3 + 2], tz);
                atomicAdd(&g_cnt[mr], 1.f);
            }
        }
        __syncwarp();
    }
}

// ---------------- node kernel (unchanged) ----------------
#define NODE_STAGE_BASE 12416
#define NODE_STAGE_STRIDE 4224
#define NODE_SMEM_FLOATS (NODE_STAGE_BASE + 8 * NODE_STAGE_STRIDE)
#define NODE_SMEM_BYTES (NODE_SMEM_FLOATS * 4)

__global__ void __launch_bounds__(256, 1) node_kernel(
    const float* __restrict__ h,
    const float* __restrict__ Wn1, const float* __restrict__ bn1,
    const float* __restrict__ Wn2, const float* __restrict__ bn2,
    float* __restrict__ out_h, float* __restrict__ out_c)
{
    extern __shared__ float s[];
    const int tid = threadIdx.x;
    for (int i = tid; i < 8192; i += 256) s[i]         = Wn1[i];
    for (int i = tid; i < 64;   i += 256) s[8192 + i]  = bn1[i];
    for (int i = tid; i < 4096; i += 256) s[8256 + i]  = Wn2[i];
    for (int i = tid; i < 64;   i += 256) s[12352 + i] = bn2[i];
    __syncthreads();

    const int warp = tid >> 5, lane = tid & 31;
    float* stage = s + NODE_STAGE_BASE + warp * NODE_STAGE_STRIDE;

    const int nbase = blockIdx.x * 256 + warp * 32;
    const int n = nbase + lane;

    #pragma unroll 4
    for (int r = 0; r < 32; r++) {
        const int nr = nbase + r;
        if (nr < NN) {
            const float* hp = h + (size_t)nr * 64;
            const float* ap = g_agg + (size_t)nr * 64;
            stage[(lane)      * 33 + r] = hp[lane];
            stage[(lane + 32) * 33 + r] = hp[lane + 32];
            stage[(lane + 64) * 33 + r] = ap[lane];
            stage[(lane + 96) * 33 + r] = ap[lane + 32];
        } else {
            stage[(lane)      * 33 + r] = 0.f;
            stage[(lane + 32) * 33 + r] = 0.f;
            stage[(lane + 64) * 33 + r] = 0.f;
            stage[(lane + 96) * 33 + r] = 0.f;
        }
    }
    __syncwarp();

    uint64_t acc2[32];
    float m[64];

    {
        const uint64_t* b2 = (const uint64_t*)(s + 8192);
        #pragma unroll
        for (int t = 0; t < 32; t++) acc2[t] = b2[t];
    }
    for (int k = 0; k < 128; k++) {
        const float x = stage[k * 33 + lane];
        const uint64_t xx = pack2(x, x);
        const ulonglong2* w = (const ulonglong2*)(s + k * 64);
        #pragma unroll
        for (int t = 0; t < 16; t++) {
            ulonglong2 wv = w[t];
            fma2(acc2[2 * t + 0], xx, wv.x);
            fma2(acc2[2 * t + 1], xx, wv.y);
        }
    }
    #pragma unroll
    for (int t = 0; t < 32; t++) {
        float a, b; unpack2(acc2[t], a, b);
        m[2 * t + 0] = fmaxf(a, 0.f);
        m[2 * t + 1] = fmaxf(b, 0.f);
    }

    {
        const uint64_t* b2 = (const uint64_t*)(s + 12352);
        #pragma unroll
        for (int t = 0; t < 32; t++) acc2[t] = b2[t];
    }
    #pragma unroll
    for (int k = 0; k < 64; k++) {
        const uint64_t xx = pack2(m[k], m[k]);
        const ulonglong2* w = (const ulonglong2*)(s + 8256 + k * 64);
        #pragma unroll
        for (int t = 0; t < 16; t++) {
            ulonglong2 wv = w[t];
            fma2(acc2[2 * t + 0], xx, wv.x);
            fma2(acc2[2 * t + 1], xx, wv.y);
        }
    }

    if (n < NN) {
        float* op = out_h + (size_t)n * 64;
        #pragma unroll
        for (int t = 0; t < 16; t++) {
            float a, b, c, d;
            unpack2(acc2[2 * t + 0], a, b);
            unpack2(acc2[2 * t + 1], c, d);
            float4 v;
            v.x = stage[(4 * t + 0) * 33 + lane] + a;
            v.y = stage[(4 * t + 1) * 33 + lane] + b;
            v.z = stage[(4 * t + 2) * 33 + lane] + c;
            v.w = stage[(4 * t + 3) * 33 + lane] + d;
            *(float4*)(op + 4 * t) = v;
        }
        const float inv = 1.f / fmaxf(g_cnt[n], 1.f);
        out_c[n * 3 + 0] = g_trans[n * 3 + 0] * inv;
        out_c[n * 3 + 1] = g_trans[n * 3 + 1] * inv;
        out_c[n * 3 + 2] = g_trans[n * 3 + 2] * inv;
    }
}

// ---------------- launch ----------------
extern "C" void kernel_launch(void* const* d_in, const int* in_sizes, int n_in,
                              void* d_out, int out_size)
{
    const float* h     = (const float*)d_in[0];
    const float* coord = (const float*)d_in[1];
    const int*   ei    = (const int*)  d_in[2];
    const float* We1 = (const float*)d_in[3];
    const float* be1 = (const float*)d_in[4];
    const float* We2 = (const float*)d_in[5];
    const float* be2 = (const float*)d_in[6];
    const float* Wn1 = (const float*)d_in[7];
    const float* bn1 = (const float*)d_in[8];
    const float* Wn2 = (const float*)d_in[9];
    const float* bn2 = (const float*)d_in[10];
    const float* Wc1 = (const float*)d_in[11];
    const float* bc1 = (const float*)d_in[12];
    const float* Wc2 = (const float*)d_in[13];

    float* out_h = (float*)d_out;                   // [N, 64]
    float* out_c = (float*)d_out + (size_t)NN * DD; // [N, 3]

    cudaFuncSetAttribute(pq_kernel,   cudaFuncAttributeMaxDynamicSharedMemorySize, PQ_SMEM_BYTES);
    cudaFuncSetAttribute(edge_kernel, cudaFuncAttributeMaxDynamicSharedMemorySize, EDGE_SMEM_BYTES);
    cudaFuncSetAttribute(node_kernel, cudaFuncAttributeMaxDynamicSharedMemorySize, NODE_SMEM_BYTES);

    zero_kernel<<<1024, 256>>>();
    pq_kernel<<<(NN + 255) / 256, 256, PQ_SMEM_BYTES>>>(h, We1, be1);
    edge_kernel<<<444, 128, EDGE_SMEM_BYTES>>>(coord, ei, We1, We2, Wc1, be2, bc1, Wc2);
    node_kernel<<<(NN + 255) / 256, 256, NODE_SMEM_BYTES>>>(h, Wn1, bn1, Wn2, bn2,
                                                            out_h, out_c);
}

// round 11
// speedup vs baseline: 1.7328x; 1.0940x over previous
#include <cuda_runtime.h>
#include <cuda_bf16.h>
#include <mma.h>
#include <cstdint>

using namespace nvcuda;

#define NN 50000
#define EE 1000000
#define DD 64
#define NWT (EE / 16)     // 62500 edge warp-tiles
#define NNT (NN / 16)     // 3125 node warp-tiles, exact

// ---------------- scratch (device globals; no allocation allowed) ----------------
__device__ float g_agg[NN * DD];
__device__ float g_trans[NN * 3];
__device__ float g_cnt[NN];
__device__ float g_P[NN * DD];       // h @ We1[0:64] + be1
__device__ float g_Q[NN * DD];       // h @ We1[64:128]

__device__ __forceinline__ void red2(float* p, float a, float b) {
    asm volatile("red.global.add.v2.f32 [%0], {%1, %2};"
                 :: "l"(p), "f"(a), "f"(b) : "memory");
}
__device__ __forceinline__ uint64_t pack2(float x, float y) {
    uint64_t r; asm("mov.b64 %0, {%1, %2};" : "=l"(r) : "f"(x), "f"(y)); return r;
}
__device__ __forceinline__ void unpack2(uint64_t v, float& x, float& y) {
    asm("mov.b64 {%0, %1}, %2;" : "=f"(x), "=f"(y) : "l"(v));
}
__device__ __forceinline__ void fma2(uint64_t& acc, uint64_t a, uint64_t b) {
    asm("fma.rn.f32x2 %0, %1, %2, %0;" : "+l"(acc) : "l"(a), "l"(b));
}
__device__ __forceinline__ uint32_t bf2u(__nv_bfloat162 v) {
    uint32_t u; memcpy(&u, &v, 4); return u;
}

// generalized warp-local hi/lo GEMM: D[16 x 64] = A[16 x 16*KSTEPS] @ W
template<int KSTEPS, int ASTRIDE>
__device__ __forceinline__ void gemm_hilo_g(
    const __nv_bfloat16* Ah, const __nv_bfloat16* Al,
    const __nv_bfloat16* Wh, const __nv_bfloat16* Wl,
    float* Dp)
{
    wmma::fragment<wmma::accumulator, 16, 16, 16, float> acc[4];
    #pragma unroll
    for (int ct = 0; ct < 4; ct++) wmma::fill_fragment(acc[ct], 0.f);

    #pragma unroll
    for (int k0 = 0; k0 < KSTEPS; k0++) {
        wmma::fragment<wmma::matrix_a, 16, 16, 16, __nv_bfloat16, wmma::row_major> a_h, a_l;
        wmma::load_matrix_sync(a_h, Ah + k0 * 16, ASTRIDE);
        wmma::load_matrix_sync(a_l, Al + k0 * 16, ASTRIDE);
        #pragma unroll
        for (int ct = 0; ct < 4; ct++) {
            wmma::fragment<wmma::matrix_b, 16, 16, 16, __nv_bfloat16, wmma::row_major> b_h, b_l;
            wmma::load_matrix_sync(b_h, Wh + k0 * 16 * 72 + ct * 16, 72);
            wmma::load_matrix_sync(b_l, Wl + k0 * 16 * 72 + ct * 16, 72);
            wmma::mma_sync(acc[ct], a_h, b_h, acc[ct]);
            wmma::mma_sync(acc[ct], a_l, b_h, acc[ct]);
            wmma::mma_sync(acc[ct], a_h, b_l, acc[ct]);
        }
    }
    #pragma unroll
    for (int ct = 0; ct < 4; ct++)
        wmma::store_matrix_sync(Dp + ct * 16, acc[ct], 68, wmma::mem_row_major);
}

// hi/lo split of weight matrix W[rows x 64] into smem [k][n] stride 72
__device__ __forceinline__ void split_weights(
    const float* __restrict__ W, char* hDst, char* lDst, int rows, int tid, int nthr)
{
    for (int i = tid; i < rows * 64; i += nthr) {
        const int k = i >> 6, n = i & 63;
        float v = W[i];
        __nv_bfloat16 hb = __float2bfloat16(v);
        __nv_bfloat16 lb = __float2bfloat16(v - __bfloat162float(hb));
        ((__nv_bfloat16*)hDst)[k * 72 + n] = hb;
        ((__nv_bfloat16*)lDst)[k * 72 + n] = lb;
    }
}

// ---------------- zero scratch ----------------
__global__ void zero_kernel() {
    int i = blockIdx.x * blockDim.x + threadIdx.x;
    int stride = gridDim.x * blockDim.x;
    for (int j = i; j < NN * DD; j += stride) g_agg[j] = 0.f;
    for (int j = i; j < NN * 3;  j += stride) g_trans[j] = 0.f;
    for (int j = i; j < NN;      j += stride) g_cnt[j] = 0.f;
}

// ---------------- pq kernel (unchanged from R10) ----------------
#define PQ_STAGE_BASE 8256
#define PQ_STAGE_STRIDE 2112
#define PQ_SMEM_FLOATS (PQ_STAGE_BASE + 8 * PQ_STAGE_STRIDE)
#define PQ_SMEM_BYTES (PQ_SMEM_FLOATS * 4)

__global__ void __launch_bounds__(256, 1) pq_kernel(
    const float* __restrict__ h,
    const float* __restrict__ We1, const float* __restrict__ be1)
{
    extern __shared__ float s[];
    const int tid = threadIdx.x;
    for (int i = tid; i < 8192; i += 256) s[i] = We1[i];
    for (int i = tid; i < 64;   i += 256) s[8192 + i] = be1[i];
    __syncthreads();

    const int warp = tid >> 5, lane = tid & 31;
    float* stage = s + PQ_STAGE_BASE + warp * PQ_STAGE_STRIDE;
    const int nbase = blockIdx.x * 256 + warp * 32;
    const int n = nbase + lane;

    #pragma unroll 4
    for (int r = 0; r < 32; r++) {
        const int nr = nbase + r;
        if (nr < NN) {
            const float* hp = h + (size_t)nr * 64;
            stage[lane * 33 + r]        = hp[lane];
            stage[(lane + 32) * 33 + r] = hp[lane + 32];
        } else {
            stage[lane * 33 + r]        = 0.f;
            stage[(lane + 32) * 33 + r] = 0.f;
        }
    }
    __syncwarp();

    uint64_t acc2[32];
    {
        const uint64_t* b2 = (const uint64_t*)(s + 8192);
        #pragma unroll
        for (int t = 0; t < 32; t++) acc2[t] = b2[t];
    }
    for (int k = 0; k < 64; k++) {
        const float x = stage[k * 33 + lane];
        const uint64_t xx = pack2(x, x);
        const ulonglong2* w = (const ulonglong2*)(s + k * 64);
        #pragma unroll
        for (int t = 0; t < 16; t++) {
            ulonglong2 wv = w[t];
            fma2(acc2[2 * t + 0], xx, wv.x);
            fma2(acc2[2 * t + 1], xx, wv.y);
        }
    }
    if (n < NN) {
        float* op = g_P + (size_t)n * 64;
        #pragma unroll
        for (int t = 0; t < 16; t++) {
            float a, b, c, d;
            unpack2(acc2[2 * t + 0], a, b);
            unpack2(acc2[2 * t + 1], c, d);
            float4 v; v.x = a; v.y = b; v.z = c; v.w = d;
            *(float4*)(op + 4 * t) = v;
        }
    }

    #pragma unroll
    for (int t = 0; t < 32; t++) acc2[t] = 0ull;
    for (int k = 0; k < 64; k++) {
        const float x = stage[k * 33 + lane];
        const uint64_t xx = pack2(x, x);
        const ulonglong2* w = (const ulonglong2*)(s + (64 + k) * 64);
        #pragma unroll
        for (int t = 0; t < 16; t++) {
            ulonglong2 wv = w[t];
            fma2(acc2[2 * t + 0], xx, wv.x);
            fma2(acc2[2 * t + 1], xx, wv.y);
        }
    }
    if (n < NN) {
        float* op = g_Q + (size_t)n * 64;
        #pragma unroll
        for (int t = 0; t < 16; t++) {
            float a, b, c, d;
            unpack2(acc2[2 * t + 0], a, b);
            unpack2(acc2[2 * t + 1], c, d);
            float4 v; v.x = a; v.y = b; v.z = c; v.w = d;
            *(float4*)(op + 4 * t) = v;
        }
    }
}

// ---------------- edge kernel (unchanged from R10) ----------------
#define EB_WE2H 4096
#define EB_WE2L 13312
#define EB_WC1H 22528
#define EB_WC1L 31744
#define EB_BLK  40960
#define BLK_STRIDE 8960
#define BLK_AH 4352
#define BLK_AL 6656
#define EDGE_SMEM_BYTES (EB_BLK + 4 * BLK_STRIDE)   // 76800

__global__ void __launch_bounds__(128, 3) edge_kernel(
    const float* __restrict__ coord,
    const int* __restrict__ ei,
    const float* __restrict__ We1,   // row 128 only
    const float* __restrict__ We2,
    const float* __restrict__ Wc1, const float* __restrict__ be2,
    const float* __restrict__ bc1, const float* __restrict__ Wc2)
{
    extern __shared__ __align__(16) char sc[];
    float* s = (float*)sc;

    const int tid = threadIdx.x;
    const int wid = tid >> 5, lane = tid & 31;

    for (int i = tid; i < 64; i += 128) {
        s[i]        = We1[128 * 64 + i];
        s[64 + i]   = be2[i];
        s[128 + i]  = bc1[i];
        s[192 + i]  = Wc2[i];
    }
    split_weights(We2, sc + EB_WE2H, sc + EB_WE2L, 64, tid, 128);
    split_weights(Wc1, sc + EB_WC1H, sc + EB_WC1L, 64, tid, 128);
    __syncthreads();

    char* ab = sc + EB_BLK + wid * BLK_STRIDE;
    const unsigned FULL = 0xFFFFFFFFu;

    const float wl0 = s[2 * lane],       wl1 = s[2 * lane + 1];
    const float b20 = s[64 + 2 * lane],  b21 = s[64 + 2 * lane + 1];

    const int r2 = lane >> 1;
    const int hh = lane & 1;
    const int c0 = hh * 32;

    const int gw = blockIdx.x * 4 + wid;
    const int nw = gridDim.x * 4;

    for (int wt = gw; wt < NWT; wt += nw) {
        int row = 0, col = 0; float dx = 0.f, dy = 0.f, dz = 0.f, rad = 0.f;
        if (lane < 16) {
            const int e = wt * 16 + lane;
            row = ei[e];
            col = ei[EE + e];
            dx = coord[row * 3 + 0] - coord[col * 3 + 0];
            dy = coord[row * 3 + 1] - coord[col * 3 + 1];
            dz = coord[row * 3 + 2] - coord[col * 3 + 2];
            rad = dx * dx + dy * dy + dz * dz;
        }

        #pragma unroll
        for (int r = 0; r < 16; r++) {
            const int er = __shfl_sync(FULL, row, r);
            const int ec = __shfl_sync(FULL, col, r);
            const float rr = __shfl_sync(FULL, rad, r);
            const float2 p = *(const float2*)(g_P + (size_t)er * 64 + 2 * lane);
            const float2 q = *(const float2*)(g_Q + (size_t)ec * 64 + 2 * lane);
            const float v0 = fmaxf(fmaf(rr, wl0, p.x + q.x), 0.f);
            const float v1 = fmaxf(fmaf(rr, wl1, p.y + q.y), 0.f);
            __nv_bfloat162 hb = __floats2bfloat162_rn(v0, v1);
            __nv_bfloat162 lb = __floats2bfloat162_rn(v0 - __bfloat162float(hb.x),
                                                      v1 - __bfloat162float(hb.y));
            *(uint32_t*)(ab + BLK_AH + r * 144 + lane * 4) = bf2u(hb);
            *(uint32_t*)(ab + BLK_AL + r * 144 + lane * 4) = bf2u(lb);
        }
        __syncwarp();

        gemm_hilo_g<4, 72>((const __nv_bfloat16*)(ab + BLK_AH),
                           (const __nv_bfloat16*)(ab + BLK_AL),
                           (const __nv_bfloat16*)(sc + EB_WE2H),
                           (const __nv_bfloat16*)(sc + EB_WE2L),
                           (float*)ab);
        __syncwarp();

        #pragma unroll
        for (int r = 0; r < 16; r++) {
            const int er = __shfl_sync(FULL, row, r);
            const float2 d = *(const float2*)((float*)ab + r * 68 + 2 * lane);
            const float e0 = fmaxf(d.x + b20, 0.f);
            const float e1 = fmaxf(d.y + b21, 0.f);
            red2(g_agg + (size_t)er * 64 + 2 * lane, e0, e1);
            __nv_bfloat162 hb = __floats2bfloat162_rn(e0, e1);
            __nv_bfloat162 lb = __floats2bfloat162_rn(e0 - __bfloat162float(hb.x),
                                                      e1 - __bfloat162float(hb.y));
            *(uint32_t*)(ab + BLK_AH + r * 144 + lane * 4) = bf2u(hb);
            *(uint32_t*)(ab + BLK_AL + r * 144 + lane * 4) = bf2u(lb);
        }
        __syncwarp();

        gemm_hilo_g<4, 72>((const __nv_bfloat16*)(ab + BLK_AH),
                           (const __nv_bfloat16*)(ab + BLK_AL),
                           (const __nv_bfloat16*)(sc + EB_WC1H),
                           (const __nv_bfloat16*)(sc + EB_WC1L),
                           (float*)ab);
        __syncwarp();

        {
            const float4* Dr = (const float4*)((float*)ab + r2 * 68 + c0);
            const float4* bb = (const float4*)(s + 128 + c0);
            const float4* wc = (const float4*)(s + 192 + c0);
            float g = 0.f;
            #pragma unroll
            for (int j = 0; j < 8; j++) {
                float4 d = Dr[j], b = bb[j], w = wc[j];
                g += fmaxf(d.x + b.x, 0.f) * w.x;
                g += fmaxf(d.y + b.y, 0.f) * w.y;
                g += fmaxf(d.z + b.z, 0.f) * w.z;
                g += fmaxf(d.w + b.w, 0.f) * w.w;
            }
            g += __shfl_xor_sync(FULL, g, 1);
            const int   mr  = __shfl_sync(FULL, row, r2);
            const float dxr = __shfl_sync(FULL, dx, r2);
            const float dyr = __shfl_sync(FULL, dy, r2);
            const float dzr = __shfl_sync(FULL, dz, r2);
            if (hh == 0) {
                const float tx = fminf(fmaxf(dxr * g, -100.f), 100.f);
                const float ty = fminf(fmaxf(dyr * g, -100.f), 100.f);
                const float tz = fminf(fmaxf(dzr * g, -100.f), 100.f);
                atomicAdd(&g_trans[mr * 3 + 0], tx);
                atomicAdd(&g_trans[mr * 3 + 1], ty);
                atomicAdd(&g_trans[mr * 3 + 2], tz);
                atomicAdd(&g_cnt[mr], 1.f);
            }
        }
        __syncwarp();
    }
}

// ---------------- node kernel: wmma hi/lo, persistent, warp-autonomous ----------------
// 256 threads/CTA, grid 148 (1 CTA/SM). Warp-tile = 16 consecutive nodes.
// SMEM byte map:
//   floats s[]: bn2 @0 (64), bn1 @64 (64)
//   W1 hi/lo [k=128][n] stride 72: N1H @1024 (18432), N1L @19456
//   W2 hi/lo [k=64][n]  stride 72: N2H @37888 (9216), N2L @47104
//   per-warp blocks @57344, 8 x 17664:
//     [D 16x68f = 4352 | A1h 16x136bf = 4352 | A1l 4352 | A2h 16x72bf = 2304 | A2l 2304]
#define ND_N1H 1024
#define ND_N1L 19456
#define ND_N2H 37888
#define ND_N2L 47104
#define ND_BLK 57344
#define ND_STRIDE 17664
#define ND_A1H 4352
#define ND_A1L 8704
#define ND_A2H 13056
#define ND_A2L 15360
#define NODE_SMEM_BYTES (ND_BLK + 8 * ND_STRIDE)   // 198656

__global__ void __launch_bounds__(256, 1) node_kernel(
    const float* __restrict__ h,
    const float* __restrict__ Wn1, const float* __restrict__ bn1,
    const float* __restrict__ Wn2, const float* __restrict__ bn2,
    float* __restrict__ out_h, float* __restrict__ out_c)
{
    extern __shared__ __align__(16) char sc[];
    float* s = (float*)sc;

    const int tid = threadIdx.x;
    const int wid = tid >> 5, lane = tid & 31;

    for (int i = tid; i < 64; i += 256) {
        s[i]      = bn2[i];
        s[64 + i] = bn1[i];
    }
    split_weights(Wn1, sc + ND_N1H, sc + ND_N1L, 128, tid, 256);
    split_weights(Wn2, sc + ND_N2H, sc + ND_N2L, 64, tid, 256);
    __syncthreads();

    char* ab = sc + ND_BLK + wid * ND_STRIDE;
    const float b1a = s[64 + 2 * lane], b1b = s[64 + 2 * lane + 1];
    const float b2a = s[2 * lane],      b2b = s[2 * lane + 1];

    const int gw = blockIdx.x * 8 + wid;
    const int nw = gridDim.x * 8;

    for (int wt = gw; wt < NNT; wt += nw) {
        const int nbase = wt * 16;

        // ---- build A1 = [h | agg], 16x128 hi/lo; lane covers cols 4*lane..4*lane+3
        {
            const int src_agg = lane >= 16;
            const int cb = (lane & 15) * 4;   // column within the 64-wide source
            #pragma unroll
            for (int r = 0; r < 16; r++) {
                const size_t base = (size_t)(nbase + r) * 64 + cb;
                float4 v = src_agg ? *(const float4*)(g_agg + base)
                                   : *(const float4*)(h + base);
                __nv_bfloat162 h01 = __floats2bfloat162_rn(v.x, v.y);
                __nv_bfloat162 h23 = __floats2bfloat162_rn(v.z, v.w);
                __nv_bfloat162 l01 = __floats2bfloat162_rn(v.x - __bfloat162float(h01.x),
                                                           v.y - __bfloat162float(h01.y));
                __nv_bfloat162 l23 = __floats2bfloat162_rn(v.z - __bfloat162float(h23.x),
                                                           v.w - __bfloat162float(h23.y));
                *(uint2*)(ab + ND_A1H + r * 272 + lane * 8) = make_uint2(bf2u(h01), bf2u(h23));
                *(uint2*)(ab + ND_A1L + r * 272 + lane * 8) = make_uint2(bf2u(l01), bf2u(l23));
            }
        }
        __syncwarp();

        // ---- GEMM1: D = A1 @ Wn1 ----
        gemm_hilo_g<8, 136>((const __nv_bfloat16*)(ab + ND_A1H),
                            (const __nv_bfloat16*)(ab + ND_A1L),
                            (const __nv_bfloat16*)(sc + ND_N1H),
                            (const __nv_bfloat16*)(sc + ND_N1L),
                            (float*)ab);
        __syncwarp();

        // ---- epilogue 1: hidden = relu(D + bn1) -> A2 hi/lo ----
        #pragma unroll
        for (int r = 0; r < 16; r++) {
            const float2 d = *(const float2*)((float*)ab + r * 68 + 2 * lane);
            const float e0 = fmaxf(d.x + b1a, 0.f);
            const float e1 = fmaxf(d.y + b1b, 0.f);
            __nv_bfloat162 hb = __floats2bfloat162_rn(e0, e1);
            __nv_bfloat162 lb = __floats2bfloat162_rn(e0 - __bfloat162float(hb.x),
                                                      e1 - __bfloat162float(hb.y));
            *(uint32_t*)(ab + ND_A2H + r * 144 + lane * 4) = bf2u(hb);
            *(uint32_t*)(ab + ND_A2L + r * 144 + lane * 4) = bf2u(lb);
        }
        __syncwarp();

        // ---- GEMM2: D = hidden @ Wn2 ----
        gemm_hilo_g<4, 72>((const __nv_bfloat16*)(ab + ND_A2H),
                           (const __nv_bfloat16*)(ab + ND_A2L),
                           (const __nv_bfloat16*)(sc + ND_N2H),
                           (const __nv_bfloat16*)(sc + ND_N2L),
                           (float*)ab);
        __syncwarp();

        // ---- final: out = h + D + bn2; coords ----
        #pragma unroll
        for (int r = 0; r < 16; r++) {
            const size_t base = (size_t)(nbase + r) * 64 + 2 * lane;
            const float2 hv = *(const float2*)(h + base);
            const float2 dv = *(const float2*)((float*)ab + r * 68 + 2 * lane);
            float2 o;
            o.x = hv.x + dv.x + b2a;
            o.y = hv.y + dv.y + b2b;
            *(float2*)(out_h + base) = o;
        }
        if (lane < 16) {
            const int n = nbase + lane;
            const float inv = 1.f / fmaxf(g_cnt[n], 1.f);
            out_c[n * 3 + 0] = g_trans[n * 3 + 0] * inv;
            out_c[n * 3 + 1] = g_trans[n * 3 + 1] * inv;
            out_c[n * 3 + 2] = g_trans[n * 3 + 2] * inv;
        }
        __syncwarp();
    }
}

// ---------------- launch ----------------
extern "C" void kernel_launch(void* const* d_in, const int* in_sizes, int n_in,
                              void* d_out, int out_size)
{
    const float* h     = (const float*)d_in[0];
    const float* coord = (const float*)d_in[1];
    const int*   ei    = (const int*)  d_in[2];
    const float* We1 = (const float*)d_in[3];
    const float* be1 = (const float*)d_in[4];
    const float* We2 = (const float*)d_in[5];
    const float* be2 = (const float*)d_in[6];
    const float* Wn1 = (const float*)d_in[7];
    const float* bn1 = (const float*)d_in[8];
    const float* Wn2 = (const float*)d_in[9];
    const float* bn2 = (const float*)d_in[10];
    const float* Wc1 = (const float*)d_in[11];
    const float* bc1 = (const float*)d_in[12];
    const float* Wc2 = (const float*)d_in[13];

    float* out_h = (float*)d_out;                   // [N, 64]
    float* out_c = (float*)d_out + (size_t)NN * DD; // [N, 3]

    cudaFuncSetAttribute(pq_kernel,   cudaFuncAttributeMaxDynamicSharedMemorySize, PQ_SMEM_BYTES);
    cudaFuncSetAttribute(edge_kernel, cudaFuncAttributeMaxDynamicSharedMemorySize, EDGE_SMEM_BYTES);
    cudaFuncSetAttribute(node_kernel, cudaFuncAttributeMaxDynamicSharedMemorySize, NODE_SMEM_BYTES);

    zero_kernel<<<1024, 256>>>();
    pq_kernel<<<(NN + 255) / 256, 256, PQ_SMEM_BYTES>>>(h, We1, be1);
    edge_kernel<<<444, 128, EDGE_SMEM_BYTES>>>(coord, ei, We1, We2, Wc1, be2, bc1, Wc2);
    node_kernel<<<148, 256, NODE_SMEM_BYTES>>>(h, Wn1, bn1, Wn2, bn2, out_h, out_c);
}

// round 12
// speedup vs baseline: 1.9397x; 1.1194x over previous
#include <cuda_runtime.h>
#include <cuda_bf16.h>
#include <mma.h>
#include <cstdint>

using namespace nvcuda;

#define NN 50000
#define EE 1000000
#define DD 64
#define NWT (EE / 16)     // 62500 edge warp-tiles
#define NNT (NN / 16)     // 3125 node warp-tiles, exact

// ---------------- scratch (device globals; no allocation allowed) ----------------
__device__ float g_agg[NN * DD];
__device__ float g_trans[NN * 3];
__device__ float g_cnt[NN];
__device__ float g_P[NN * DD];       // h @ We1[0:64] + be1
__device__ float g_Q[NN * DD];       // h @ We1[64:128]

__device__ __forceinline__ void red4(float* p, float a, float b, float c, float d) {
    asm volatile("red.global.add.v4.f32 [%0], {%1, %2, %3, %4};"
                 :: "l"(p), "f"(a), "f"(b), "f"(c), "f"(d) : "memory");
}
__device__ __forceinline__ uint32_t bf2u(__nv_bfloat162 v) {
    uint32_t u; memcpy(&u, &v, 4); return u;
}

// generalized warp-local hi/lo GEMM: D[16 x 64] = A[16 x 16*KSTEPS] @ W
template<int KSTEPS, int ASTRIDE>
__device__ __forceinline__ void gemm_hilo_g(
    const __nv_bfloat16* Ah, const __nv_bfloat16* Al,
    const __nv_bfloat16* Wh, const __nv_bfloat16* Wl,
    float* Dp)
{
    wmma::fragment<wmma::accumulator, 16, 16, 16, float> acc[4];
    #pragma unroll
    for (int ct = 0; ct < 4; ct++) wmma::fill_fragment(acc[ct], 0.f);

    #pragma unroll
    for (int k0 = 0; k0 < KSTEPS; k0++) {
        wmma::fragment<wmma::matrix_a, 16, 16, 16, __nv_bfloat16, wmma::row_major> a_h, a_l;
        wmma::load_matrix_sync(a_h, Ah + k0 * 16, ASTRIDE);
        wmma::load_matrix_sync(a_l, Al + k0 * 16, ASTRIDE);
        #pragma unroll
        for (int ct = 0; ct < 4; ct++) {
            wmma::fragment<wmma::matrix_b, 16, 16, 16, __nv_bfloat16, wmma::row_major> b_h, b_l;
            wmma::load_matrix_sync(b_h, Wh + k0 * 16 * 72 + ct * 16, 72);
            wmma::load_matrix_sync(b_l, Wl + k0 * 16 * 72 + ct * 16, 72);
            wmma::mma_sync(acc[ct], a_h, b_h, acc[ct]);
            wmma::mma_sync(acc[ct], a_l, b_h, acc[ct]);
            wmma::mma_sync(acc[ct], a_h, b_l, acc[ct]);
        }
    }
    #pragma unroll
    for (int ct = 0; ct < 4; ct++)
        wmma::store_matrix_sync(Dp + ct * 16, acc[ct], 68, wmma::mem_row_major);
}

// hi/lo split of weight matrix W[rows x 64] into smem [k][n] stride 72
__device__ __forceinline__ void split_weights(
    const float* __restrict__ W, char* hDst, char* lDst, int rows, int tid, int nthr)
{
    for (int i = tid; i < rows * 64; i += nthr) {
        const int k = i >> 6, n = i & 63;
        float v = W[i];
        __nv_bfloat16 hb = __float2bfloat16(v);
        __nv_bfloat16 lb = __float2bfloat16(v - __bfloat162float(hb));
        ((__nv_bfloat16*)hDst)[k * 72 + n] = hb;
        ((__nv_bfloat16*)lDst)[k * 72 + n] = lb;
    }
}

// split float4 to hi/lo bf16 pair (uint2 each)
__device__ __forceinline__ void split4(float a, float b, float c, float d,
                                       uint2& hi, uint2& lo)
{
    __nv_bfloat162 h01 = __floats2bfloat162_rn(a, b);
    __nv_bfloat162 h23 = __floats2bfloat162_rn(c, d);
    __nv_bfloat162 l01 = __floats2bfloat162_rn(a - __bfloat162float(h01.x),
                                               b - __bfloat162float(h01.y));
    __nv_bfloat162 l23 = __floats2bfloat162_rn(c - __bfloat162float(h23.x),
                                               d - __bfloat162float(h23.y));
    hi = make_uint2(bf2u(h01), bf2u(h23));
    lo = make_uint2(bf2u(l01), bf2u(l23));
}

// ---------------- zero scratch ----------------
__global__ void zero_kernel() {
    int i = blockIdx.x * blockDim.x + threadIdx.x;
    int stride = gridDim.x * blockDim.x;
    for (int j = i; j < NN * DD; j += stride) g_agg[j] = 0.f;
    for (int j = i; j < NN * 3;  j += stride) g_trans[j] = 0.f;
    for (int j = i; j < NN;      j += stride) g_cnt[j] = 0.f;
}

// ---------------- pq kernel: wmma hi/lo, persistent ----------------
// P = h @ We1[0:64] + be1 ; Q = h @ We1[64:128]. One A build, two GEMMs.
// SMEM: be1 @0 (floats); WPh @1024, WPl @10240, WQh @19456, WQl @28672 (9216 each);
// per-warp blocks @38912, 8 x 8960: [D 4352 | Ah 2304 | Al 2304]
#define PQ_WPH 1024
#define PQ_WPL 10240
#define PQ_WQH 19456
#define PQ_WQL 28672
#define PQ_BLK 38912
#define PQ_STRIDE 8960
#define PQ_AH 4352
#define PQ_AL 6656
#define PQ_SMEM_BYTES (PQ_BLK + 8 * PQ_STRIDE)   // 110592

__global__ void __launch_bounds__(256, 1) pq_kernel(
    const float* __restrict__ h,
    const float* __restrict__ We1, const float* __restrict__ be1)
{
    extern __shared__ __align__(16) char sc[];
    float* s = (float*)sc;
    const int tid = threadIdx.x;
    const int wid = tid >> 5, lane = tid & 31;

    for (int i = tid; i < 64; i += 256) s[i] = be1[i];
    split_weights(We1,           sc + PQ_WPH, sc + PQ_WPL, 64, tid, 256);
    split_weights(We1 + 64 * 64, sc + PQ_WQH, sc + PQ_WQL, 64, tid, 256);
    __syncthreads();

    char* ab = sc + PQ_BLK + wid * PQ_STRIDE;
    const int c4 = (lane & 15) * 4;
    const int half = lane >> 4;
    const float4 bb = *(const float4*)(s + c4);

    const int gw = blockIdx.x * 8 + wid;
    const int nw = gridDim.x * 8;

    for (int wt = gw; wt < NNT; wt += nw) {
        const int nbase = wt * 16;

        // build A = h tile (2 rows per iteration)
        #pragma unroll
        for (int rr = 0; rr < 8; rr++) {
            const int r = 2 * rr + half;
            float4 v = *(const float4*)(h + (size_t)(nbase + r) * 64 + c4);
            uint2 hi, lo;
            split4(v.x, v.y, v.z, v.w, hi, lo);
            *(uint2*)(ab + PQ_AH + r * 144 + c4 * 2) = hi;
            *(uint2*)(ab + PQ_AL + r * 144 + c4 * 2) = lo;
        }
        __syncwarp();

        // GEMM P
        gemm_hilo_g<4, 72>((const __nv_bfloat16*)(ab + PQ_AH),
                           (const __nv_bfloat16*)(ab + PQ_AL),
                           (const __nv_bfloat16*)(sc + PQ_WPH),
                           (const __nv_bfloat16*)(sc + PQ_WPL),
                           (float*)ab);
        __syncwarp();
        #pragma unroll
        for (int rr = 0; rr < 8; rr++) {
            const int r = 2 * rr + half;
            float4 d = *(const float4*)((float*)ab + r * 68 + c4);
            float4 o; o.x = d.x + bb.x; o.y = d.y + bb.y; o.z = d.z + bb.z; o.w = d.w + bb.w;
            *(float4*)(g_P + (size_t)(nbase + r) * 64 + c4) = o;
        }
        __syncwarp();

        // GEMM Q (A unchanged)
        gemm_hilo_g<4, 72>((const __nv_bfloat16*)(ab + PQ_AH),
                           (const __nv_bfloat16*)(ab + PQ_AL),
                           (const __nv_bfloat16*)(sc + PQ_WQH),
                           (const __nv_bfloat16*)(sc + PQ_WQL),
                           (float*)ab);
        __syncwarp();
        #pragma unroll
        for (int rr = 0; rr < 8; rr++) {
            const int r = 2 * rr + half;
            float4 d = *(const float4*)((float*)ab + r * 68 + c4);
            *(float4*)(g_Q + (size_t)(nbase + r) * 64 + c4) = d;
        }
        __syncwarp();
    }
}

// ---------------- edge kernel: warp-autonomous, float4/red4 paths ----------------
#define EB_WE2H 4096
#define EB_WE2L 13312
#define EB_WC1H 22528
#define EB_WC1L 31744
#define EB_BLK  40960
#define BLK_STRIDE 8960
#define BLK_AH 4352
#define BLK_AL 6656
#define EDGE_SMEM_BYTES (EB_BLK + 4 * BLK_STRIDE)   // 76800

__global__ void __launch_bounds__(128, 3) edge_kernel(
    const float* __restrict__ coord,
    const int* __restrict__ ei,
    const float* __restrict__ We1,   // row 128 only
    const float* __restrict__ We2,
    const float* __restrict__ Wc1, const float* __restrict__ be2,
    const float* __restrict__ bc1, const float* __restrict__ Wc2)
{
    extern __shared__ __align__(16) char sc[];
    float* s = (float*)sc;

    const int tid = threadIdx.x;
    const int wid = tid >> 5, lane = tid & 31;

    for (int i = tid; i < 64; i += 128) {
        s[i]        = We1[128 * 64 + i];
        s[64 + i]   = be2[i];
        s[128 + i]  = bc1[i];
        s[192 + i]  = Wc2[i];
    }
    split_weights(We2, sc + EB_WE2H, sc + EB_WE2L, 64, tid, 128);
    split_weights(Wc1, sc + EB_WC1H, sc + EB_WC1L, 64, tid, 128);
    __syncthreads();

    char* ab = sc + EB_BLK + wid * BLK_STRIDE;
    const unsigned FULL = 0xFFFFFFFFu;

    const int c4 = (lane & 15) * 4;
    const int half = lane >> 4;
    const float4 w4 = *(const float4*)(s + c4);        // w128 cols
    const float4 b4 = *(const float4*)(s + 64 + c4);   // be2 cols

    const int r2 = lane >> 1;
    const int hh = lane & 1;
    const int c0 = hh * 32;

    const int gw = blockIdx.x * 4 + wid;
    const int nw = gridDim.x * 4;

    for (int wt = gw; wt < NWT; wt += nw) {
        int row = 0, col = 0; float dx = 0.f, dy = 0.f, dz = 0.f, rad = 0.f;
        if (lane < 16) {
            const int e = wt * 16 + lane;
            row = ei[e];
            col = ei[EE + e];
            dx = coord[row * 3 + 0] - coord[col * 3 + 0];
            dy = coord[row * 3 + 1] - coord[col * 3 + 1];
            dz = coord[row * 3 + 2] - coord[col * 3 + 2];
            rad = dx * dx + dy * dy + dz * dz;
        }

        // ---- staging: 2 rows/iter, float4 gathers ----
        #pragma unroll
        for (int rr = 0; rr < 8; rr++) {
            const int r = 2 * rr + half;
            const int er = __shfl_sync(FULL, row, r);
            const int ec = __shfl_sync(FULL, col, r);
            const float rv = __shfl_sync(FULL, rad, r);
            const float4 p = *(const float4*)(g_P + (size_t)er * 64 + c4);
            const float4 q = *(const float4*)(g_Q + (size_t)ec * 64 + c4);
            const float v0 = fmaxf(fmaf(rv, w4.x, p.x + q.x), 0.f);
            const float v1 = fmaxf(fmaf(rv, w4.y, p.y + q.y), 0.f);
            const float v2 = fmaxf(fmaf(rv, w4.z, p.z + q.z), 0.f);
            const float v3 = fmaxf(fmaf(rv, w4.w, p.w + q.w), 0.f);
            uint2 hi, lo;
            split4(v0, v1, v2, v3, hi, lo);
            *(uint2*)(ab + BLK_AH + r * 144 + c4 * 2) = hi;
            *(uint2*)(ab + BLK_AL + r * 144 + c4 * 2) = lo;
        }
        __syncwarp();

        gemm_hilo_g<4, 72>((const __nv_bfloat16*)(ab + BLK_AH),
                           (const __nv_bfloat16*)(ab + BLK_AL),
                           (const __nv_bfloat16*)(sc + EB_WE2H),
                           (const __nv_bfloat16*)(sc + EB_WE2L),
                           (float*)ab);
        __syncwarp();

        // ---- epilogue 1: 2 rows/iter, red4 scatter ----
        #pragma unroll
        for (int rr = 0; rr < 8; rr++) {
            const int r = 2 * rr + half;
            const int er = __shfl_sync(FULL, row, r);
            const float4 d = *(const float4*)((float*)ab + r * 68 + c4);
            const float e0 = fmaxf(d.x + b4.x, 0.f);
            const float e1 = fmaxf(d.y + b4.y, 0.f);
            const float e2 = fmaxf(d.z + b4.z, 0.f);
            const float e3 = fmaxf(d.w + b4.w, 0.f);
            red4(g_agg + (size_t)er * 64 + c4, e0, e1, e2, e3);
            uint2 hi, lo;
            split4(e0, e1, e2, e3, hi, lo);
            *(uint2*)(ab + BLK_AH + r * 144 + c4 * 2) = hi;
            *(uint2*)(ab + BLK_AL + r * 144 + c4 * 2) = lo;
        }
        __syncwarp();

        gemm_hilo_g<4, 72>((const __nv_bfloat16*)(ab + BLK_AH),
                           (const __nv_bfloat16*)(ab + BLK_AL),
                           (const __nv_bfloat16*)(sc + EB_WC1H),
                           (const __nv_bfloat16*)(sc + EB_WC1L),
                           (float*)ab);
        __syncwarp();

        // ---- epilogue 2: gate -> coord atomics ----
        {
            const float4* Dr = (const float4*)((float*)ab + r2 * 68 + c0);
            const float4* bb = (const float4*)(s + 128 + c0);
            const float4* wc = (const float4*)(s + 192 + c0);
            float g = 0.f;
            #pragma unroll
            for (int j = 0; j < 8; j++) {
                float4 d = Dr[j], b = bb[j], w = wc[j];
                g += fmaxf(d.x + b.x, 0.f) * w.x;
                g += fmaxf(d.y + b.y, 0.f) * w.y;
                g += fmaxf(d.z + b.z, 0.f) * w.z;
                g += fmaxf(d.w + b.w, 0.f) * w.w;
            }
            g += __shfl_xor_sync(FULL, g, 1);
            const int   mr  = __shfl_sync(FULL, row, r2);
            const float dxr = __shfl_sync(FULL, dx, r2);
            const float dyr = __shfl_sync(FULL, dy, r2);
            const float dzr = __shfl_sync(FULL, dz, r2);
            if (hh == 0) {
                const float tx = fminf(fmaxf(dxr * g, -100.f), 100.f);
                const float ty = fminf(fmaxf(dyr * g, -100.f), 100.f);
                const float tz = fminf(fmaxf(dzr * g, -100.f), 100.f);
                atomicAdd(&g_trans[mr * 3 + 0], tx);
                atomicAdd(&g_trans[mr * 3 + 1], ty);
                atomicAdd(&g_trans[mr * 3 + 2], tz);
                atomicAdd(&g_cnt[mr], 1.f);
            }
        }
        __syncwarp();
    }
}

// ---------------- node kernel (unchanged from R11) ----------------
#define ND_N1H 1024
#define ND_N1L 19456
#define ND_N2H 37888
#define ND_N2L 47104
#define ND_BLK 57344
#define ND_STRIDE 17664
#define ND_A1H 4352
#define ND_A1L 8704
#define ND_A2H 13056
#define ND_A2L 15360
#define NODE_SMEM_BYTES (ND_BLK + 8 * ND_STRIDE)   // 198656

__global__ void __launch_bounds__(256, 1) node_kernel(
    const float* __restrict__ h,
    const float* __restrict__ Wn1, const float* __restrict__ bn1,
    const float* __restrict__ Wn2, const float* __restrict__ bn2,
    float* __restrict__ out_h, float* __restrict__ out_c)
{
    extern __shared__ __align__(16) char sc[];
    float* s = (float*)sc;

    const int tid = threadIdx.x;
    const int wid = tid >> 5, lane = tid & 31;

    for (int i = tid; i < 64; i += 256) {
        s[i]      = bn2[i];
        s[64 + i] = bn1[i];
    }
    split_weights(Wn1, sc + ND_N1H, sc + ND_N1L, 128, tid, 256);
    split_weights(Wn2, sc + ND_N2H, sc + ND_N2L, 64, tid, 256);
    __syncthreads();

    char* ab = sc + ND_BLK + wid * ND_STRIDE;
    const float b1a = s[64 + 2 * lane], b1b = s[64 + 2 * lane + 1];
    const float b2a = s[2 * lane],      b2b = s[2 * lane + 1];

    const int gw = blockIdx.x * 8 + wid;
    const int nw = gridDim.x * 8;

    for (int wt = gw; wt < NNT; wt += nw) {
        const int nbase = wt * 16;

        {
            const int src_agg = lane >= 16;
            const int cb = (lane & 15) * 4;
            #pragma unroll
            for (int r = 0; r < 16; r++) {
                const size_t base = (size_t)(nbase + r) * 64 + cb;
                float4 v = src_agg ? *(const float4*)(g_agg + base)
                                   : *(const float4*)(h + base);
                uint2 hi, lo;
                split4(v.x, v.y, v.z, v.w, hi, lo);
                *(uint2*)(ab + ND_A1H + r * 272 + lane * 8) = hi;
                *(uint2*)(ab + ND_A1L + r * 272 + lane * 8) = lo;
            }
        }
        __syncwarp();

        gemm_hilo_g<8, 136>((const __nv_bfloat16*)(ab + ND_A1H),
                            (const __nv_bfloat16*)(ab + ND_A1L),
                            (const __nv_bfloat16*)(sc + ND_N1H),
                            (const __nv_bfloat16*)(sc + ND_N1L),
                            (float*)ab);
        __syncwarp();

        #pragma unroll
        for (int r = 0; r < 16; r++) {
            const float2 d = *(const float2*)((float*)ab + r * 68 + 2 * lane);
            const float e0 = fmaxf(d.x + b1a, 0.f);
            const float e1 = fmaxf(d.y + b1b, 0.f);
            __nv_bfloat162 hb = __floats2bfloat162_rn(e0, e1);
            __nv_bfloat162 lb = __floats2bfloat162_rn(e0 - __bfloat162float(hb.x),
                                                      e1 - __bfloat162float(hb.y));
            *(uint32_t*)(ab + ND_A2H + r * 144 + lane * 4) = bf2u(hb);
            *(uint32_t*)(ab + ND_A2L + r * 144 + lane * 4) = bf2u(lb);
        }
        __syncwarp();

        gemm_hilo_g<4, 72>((const __nv_bfloat16*)(ab + ND_A2H),
                           (const __nv_bfloat16*)(ab + ND_A2L),
                           (const __nv_bfloat16*)(sc + ND_N2H),
                           (const __nv_bfloat16*)(sc + ND_N2L),
                           (float*)ab);
        __syncwarp();

        #pragma unroll
        for (int r = 0; r < 16; r++) {
            const size_t base = (size_t)(nbase + r) * 64 + 2 * lane;
            const float2 hv = *(const float2*)(h + base);
            const float2 dv = *(const float2*)((float*)ab + r * 68 + 2 * lane);
            float2 o;
            o.x = hv.x + dv.x + b2a;
            o.y = hv.y + dv.y + b2b;
            *(float2*)(out_h + base) = o;
        }
        if (lane < 16) {
            const int n = nbase + lane;
            const float inv = 1.f / fmaxf(g_cnt[n], 1.f);
            out_c[n * 3 + 0] = g_trans[n * 3 + 0] * inv;
            out_c[n * 3 + 1] = g_trans[n * 3 + 1] * inv;
            out_c[n * 3 + 2] = g_trans[n * 3 + 2] * inv;
        }
        __syncwarp();
    }
}

// ---------------- launch ----------------
extern "C" void kernel_launch(void* const* d_in, const int* in_sizes, int n_in,
                              void* d_out, int out_size)
{
    const float* h     = (const float*)d_in[0];
    const float* coord = (const float*)d_in[1];
    const int*   ei    = (const int*)  d_in[2];
    const float* We1 = (const float*)d_in[3];
    const float* be1 = (const float*)d_in[4];
    const float* We2 = (const float*)d_in[5];
    const float* be2 = (const float*)d_in[6];
    const float* Wn1 = (const float*)d_in[7];
    const float* bn1 = (const float*)d_in[8];
    const float* Wn2 = (const float*)d_in[9];
    const float* bn2 = (const float*)d_in[10];
    const float* Wc1 = (const float*)d_in[11];
    const float* bc1 = (const float*)d_in[12];
    const float* Wc2 = (const float*)d_in[13];

    float* out_h = (float*)d_out;                   // [N, 64]
    float* out_c = (float*)d_out + (size_t)NN * DD; // [N, 3]

    cudaFuncSetAttribute(pq_kernel,   cudaFuncAttributeMaxDynamicSharedMemorySize, PQ_SMEM_BYTES);
    cudaFuncSetAttribute(edge_kernel, cudaFuncAttributeMaxDynamicSharedMemorySize, EDGE_SMEM_BYTES);
    cudaFuncSetAttribute(node_kernel, cudaFuncAttributeMaxDynamicSharedMemorySize, NODE_SMEM_BYTES);

    zero_kernel<<<1024, 256>>>();
    pq_kernel<<<148, 256, PQ_SMEM_BYTES>>>(h, We1, be1);
    edge_kernel<<<444, 128, EDGE_SMEM_BYTES>>>(coord, ei, We1, We2, Wc1, be2, bc1, Wc2);
    node_kernel<<<148, 256, NODE_SMEM_BYTES>>>(h, Wn1, bn1, Wn2, bn2, out_h, out_c);
}